// round 1
// baseline (speedup 1.0000x reference)
#include <cuda_runtime.h>
#include <cuda_bf16.h>
#include <math.h>

// ---------------- model constants ----------------
#define VOCAB   32000
#define DMODEL  768
#define NLAYERS 2
#define DSTATE  16
#define DCONV   4
#define DINNER  1536
#define DTRANK  48
#define BB      2
#define LL      1024
#define BL      (BB*LL)          // 2048 rows

// ---------------- scratch (device globals; no cudaMalloc allowed) ----------------
__device__ float g_h   [BL * DMODEL];        // residual stream
__device__ float g_xz  [BL * 2 * DINNER];    // in_proj output
__device__ float g_xc  [BL * DINNER];        // conv+silu output
__device__ float g_xdbl[BL * (DTRANK + 2*DSTATE)]; // 80 cols
__device__ float g_dt  [BL * DINNER];
__device__ float g_y   [BL * DINNER];
__device__ float g_ln  [BL * DMODEL];

// ---------------- embedding gather ----------------
__global__ void embed_kernel(const int* __restrict__ x,
                             const float* __restrict__ emb,
                             float* __restrict__ h) {
    int idx = blockIdx.x * blockDim.x + threadIdx.x;   // over BL*DMODEL
    if (idx >= BL * DMODEL) return;
    int row = idx / DMODEL;
    int col = idx - row * DMODEL;
    h[idx] = emb[(size_t)x[row] * DMODEL + col];
}

// ---------------- generic fp32 GEMM: C(MxN) = A(MxK) * B(NxK)^T ----------------
// mode 0: store; mode 1: softplus(acc + bias[col]); mode 2: acc + C (residual, in-place)
// M must be a multiple of 64, K a multiple of 16. N handled with bounds.
__global__ __launch_bounds__(256) void gemm_nt(
    const float* __restrict__ A, const float* __restrict__ B,
    float* __restrict__ C, const float* __restrict__ bias,
    int M, int N, int K, int lda, int ldb, int ldc, int mode)
{
    __shared__ __align__(16) float As[16][68];
    __shared__ __align__(16) float Bs[16][68];
    const int bm = blockIdx.y * 64;
    const int bn = blockIdx.x * 64;
    const int tid = threadIdx.x;
    const int lrow = tid >> 2;          // 0..63
    const int lcol = (tid & 3) << 2;    // 0,4,8,12
    const int tr = (tid >> 4) << 2;     // 0..60
    const int tc = (tid & 15) << 2;     // 0..60

    float acc[4][4];
    #pragma unroll
    for (int i = 0; i < 4; i++)
        #pragma unroll
        for (int j = 0; j < 4; j++) acc[i][j] = 0.f;

    const bool bvalid = (bn + lrow) < N;
    const float* Aptr = A + (size_t)(bm + lrow) * lda + lcol;
    const float* Bptr = B + (size_t)(bn + lrow) * ldb + lcol;

    for (int k0 = 0; k0 < K; k0 += 16) {
        float4 av = *(const float4*)(Aptr + k0);
        float4 bv = make_float4(0.f, 0.f, 0.f, 0.f);
        if (bvalid) bv = *(const float4*)(Bptr + k0);
        As[lcol+0][lrow] = av.x; As[lcol+1][lrow] = av.y;
        As[lcol+2][lrow] = av.z; As[lcol+3][lrow] = av.w;
        Bs[lcol+0][lrow] = bv.x; Bs[lcol+1][lrow] = bv.y;
        Bs[lcol+2][lrow] = bv.z; Bs[lcol+3][lrow] = bv.w;
        __syncthreads();
        #pragma unroll
        for (int kk = 0; kk < 16; kk++) {
            float4 a = *(const float4*)&As[kk][tr];
            float4 b = *(const float4*)&Bs[kk][tc];
            acc[0][0] += a.x*b.x; acc[0][1] += a.x*b.y; acc[0][2] += a.x*b.z; acc[0][3] += a.x*b.w;
            acc[1][0] += a.y*b.x; acc[1][1] += a.y*b.y; acc[1][2] += a.y*b.z; acc[1][3] += a.y*b.w;
            acc[2][0] += a.z*b.x; acc[2][1] += a.z*b.y; acc[2][2] += a.z*b.z; acc[2][3] += a.z*b.w;
            acc[3][0] += a.w*b.x; acc[3][1] += a.w*b.y; acc[3][2] += a.w*b.z; acc[3][3] += a.w*b.w;
        }
        __syncthreads();
    }

    #pragma unroll
    for (int i = 0; i < 4; i++) {
        int row = bm + tr + i;
        #pragma unroll
        for (int j = 0; j < 4; j++) {
            int col = bn + tc + j;
            if (col < N) {
                float v = acc[i][j];
                if (mode == 1) {
                    v += bias[col];
                    v = (v > 20.f) ? v : log1pf(__expf(v));   // softplus
                } else if (mode == 2) {
                    v += C[(size_t)row * ldc + col];
                }
                C[(size_t)row * ldc + col] = v;
            }
        }
    }
}

// ---------------- depthwise causal conv (K=4) + SiLU ----------------
__global__ void conv_silu_kernel(const float* __restrict__ xz,   // (BL, 2*DINNER), x half
                                 const float* __restrict__ w,    // (DINNER, 4)
                                 const float* __restrict__ b,    // (DINNER)
                                 float* __restrict__ xc)         // (BL, DINNER)
{
    int idx = blockIdx.x * blockDim.x + threadIdx.x;  // over BB*LL*DINNER
    if (idx >= BL * DINNER) return;
    int d  = idx % DINNER;
    int l  = (idx / DINNER) % LL;
    int bb = idx / (DINNER * LL);
    float s = b[d];
    #pragma unroll
    for (int k = 0; k < DCONV; k++) {
        int ll = l - (DCONV - 1) + k;
        if (ll >= 0)
            s += w[d * DCONV + k] * xz[(size_t)(bb * LL + ll) * (2 * DINNER) + d];
    }
    xc[idx] = s / (1.f + __expf(-s));   // silu
}

// ---------------- selective scan (one thread per (b, d) channel) ----------------
__global__ void scan_kernel(const float* __restrict__ xc,
                            const float* __restrict__ dt,
                            const float* __restrict__ xdbl,   // (BL, 80): [dt48 | B16 | C16]
                            const float* __restrict__ xz,     // z = cols [DINNER, 2*DINNER)
                            const float* __restrict__ A_log,  // (DINNER, 16)
                            const float* __restrict__ Dp,     // (DINNER)
                            float* __restrict__ y)
{
    int c = blockIdx.x * blockDim.x + threadIdx.x;
    if (c >= BB * DINNER) return;
    int b = c / DINNER;
    int d = c - b * DINNER;

    float Av[DSTATE];
    #pragma unroll
    for (int n = 0; n < DSTATE; n++) Av[n] = -__expf(A_log[d * DSTATE + n]);
    const float Dv = Dp[d];

    float hs[DSTATE];
    #pragma unroll
    for (int n = 0; n < DSTATE; n++) hs[n] = 0.f;

    const float* dtp = dt + (size_t)b * LL * DINNER + d;
    const float* up  = xc + (size_t)b * LL * DINNER + d;
    const float* zp  = xz + (size_t)b * LL * (2 * DINNER) + DINNER + d;
    const float4* bc = (const float4*)xdbl + (size_t)b * LL * 20 + 12; // skip 48 floats
    float* yp = y + (size_t)b * LL * DINNER + d;

    for (int l = 0; l < LL; l++) {
        float dtv = dtp[(size_t)l * DINNER];
        float uv  = up [(size_t)l * DINNER];
        const float4* row = bc + (size_t)l * 20;
        float4 b0 = row[0], b1 = row[1], b2 = row[2], b3 = row[3];
        float4 c0 = row[4], c1 = row[5], c2 = row[6], c3 = row[7];
        float Bv[16] = {b0.x,b0.y,b0.z,b0.w, b1.x,b1.y,b1.z,b1.w,
                        b2.x,b2.y,b2.z,b2.w, b3.x,b3.y,b3.z,b3.w};
        float Cv[16] = {c0.x,c0.y,c0.z,c0.w, c1.x,c1.y,c1.z,c1.w,
                        c2.x,c2.y,c2.z,c2.w, c3.x,c3.y,c3.z,c3.w};
        float du = dtv * uv;
        float accv = 0.f;
        #pragma unroll
        for (int n = 0; n < DSTATE; n++) {
            float dA = __expf(dtv * Av[n]);
            hs[n] = dA * hs[n] + du * Bv[n];
            accv += hs[n] * Cv[n];
        }
        float zv = zp[(size_t)l * (2 * DINNER)];
        float silz = zv / (1.f + __expf(-zv));
        yp[(size_t)l * DINNER] = (accv + uv * Dv) * silz;
    }
}

// ---------------- layernorm (block per row) ----------------
__global__ void layernorm_kernel(const float* __restrict__ x,
                                 const float* __restrict__ w,
                                 const float* __restrict__ b,
                                 float* __restrict__ out)
{
    __shared__ float red[32];
    int row = blockIdx.x;
    const float* xr = x + (size_t)row * DMODEL;
    float s = 0.f, s2 = 0.f;
    for (int i = threadIdx.x; i < DMODEL; i += blockDim.x) {
        float v = xr[i];
        s += v; s2 += v * v;
    }
    // warp reduce
    #pragma unroll
    for (int o = 16; o > 0; o >>= 1) {
        s  += __shfl_down_sync(0xffffffff, s,  o);
        s2 += __shfl_down_sync(0xffffffff, s2, o);
    }
    int lane = threadIdx.x & 31, wid = threadIdx.x >> 5;
    if (lane == 0) { red[wid] = s; red[wid + 16] = s2; }
    __syncthreads();
    if (wid == 0) {
        int nw = blockDim.x >> 5;
        s  = (lane < nw) ? red[lane]      : 0.f;
        s2 = (lane < nw) ? red[lane + 16] : 0.f;
        #pragma unroll
        for (int o = 16; o > 0; o >>= 1) {
            s  += __shfl_down_sync(0xffffffff, s,  o);
            s2 += __shfl_down_sync(0xffffffff, s2, o);
        }
        if (lane == 0) { red[0] = s; red[1] = s2; }
    }
    __syncthreads();
    float mu  = red[0] / DMODEL;
    float var = red[1] / DMODEL - mu * mu;
    float rstd = rsqrtf(var + 1e-5f);
    for (int i = threadIdx.x; i < DMODEL; i += blockDim.x) {
        out[(size_t)row * DMODEL + i] = (xr[i] - mu) * rstd * w[i] + b[i];
    }
}

// ---------------- host launcher ----------------
extern "C" void kernel_launch(void* const* d_in, const int* in_sizes, int n_in,
                              void* d_out, int out_size)
{
    const int*   x      = (const int*)  d_in[0];
    const float* emb    = (const float*)d_in[1];
    const float* in_w   = (const float*)d_in[2];   // (2, 3072, 768)
    const float* conv_w = (const float*)d_in[3];   // (2, 1536, 4)
    const float* conv_b = (const float*)d_in[4];   // (2, 1536)
    const float* xp_w   = (const float*)d_in[5];   // (2, 80, 1536)
    const float* dt_w   = (const float*)d_in[6];   // (2, 1536, 48)
    const float* dt_b   = (const float*)d_in[7];   // (2, 1536)
    const float* A_log  = (const float*)d_in[8];   // (2, 1536, 16)
    const float* Dp     = (const float*)d_in[9];   // (2, 1536)
    const float* out_w  = (const float*)d_in[10];  // (2, 768, 1536)
    const float* ln_w   = (const float*)d_in[11];
    const float* ln_b   = (const float*)d_in[12];
    float* out = (float*)d_out;

    float *h, *xz, *xc, *xdbl, *dtb, *yb, *lnb;
    cudaGetSymbolAddress((void**)&h,    g_h);
    cudaGetSymbolAddress((void**)&xz,   g_xz);
    cudaGetSymbolAddress((void**)&xc,   g_xc);
    cudaGetSymbolAddress((void**)&xdbl, g_xdbl);
    cudaGetSymbolAddress((void**)&dtb,  g_dt);
    cudaGetSymbolAddress((void**)&yb,   g_y);
    cudaGetSymbolAddress((void**)&lnb,  g_ln);

    embed_kernel<<<(BL * DMODEL + 255) / 256, 256>>>(x, emb, h);

    for (int i = 0; i < NLAYERS; i++) {
        // in_proj: xz(2048,3072) = h(2048,768) @ in_w_i(3072,768)^T
        gemm_nt<<<dim3(2 * DINNER / 64, BL / 64), 256>>>(
            h, in_w + (size_t)i * 2 * DINNER * DMODEL, xz, nullptr,
            BL, 2 * DINNER, DMODEL, DMODEL, DMODEL, 2 * DINNER, 0);

        conv_silu_kernel<<<(BL * DINNER + 255) / 256, 256>>>(
            xz, conv_w + (size_t)i * DINNER * DCONV, conv_b + (size_t)i * DINNER, xc);

        // x_proj: xdbl(2048,80) = xc(2048,1536) @ xp_w_i(80,1536)^T
        gemm_nt<<<dim3(2, BL / 64), 256>>>(
            xc, xp_w + (size_t)i * (DTRANK + 2 * DSTATE) * DINNER, xdbl, nullptr,
            BL, DTRANK + 2 * DSTATE, DINNER, DINNER, DINNER, DTRANK + 2 * DSTATE, 0);

        // dt: dt(2048,1536) = softplus(xdbl[:, :48] @ dt_w_i(1536,48)^T + dt_b_i)
        gemm_nt<<<dim3(DINNER / 64, BL / 64), 256>>>(
            xdbl, dt_w + (size_t)i * DINNER * DTRANK, dtb, dt_b + (size_t)i * DINNER,
            BL, DINNER, DTRANK, DTRANK + 2 * DSTATE, DTRANK, DINNER, 1);

        scan_kernel<<<(BB * DINNER + 255) / 256, 256>>>(
            xc, dtb, xdbl, xz, A_log + (size_t)i * DINNER * DSTATE,
            Dp + (size_t)i * DINNER, yb);

        // out_proj + residual: h += y(2048,1536) @ out_w_i(768,1536)^T
        gemm_nt<<<dim3(DMODEL / 64, BL / 64), 256>>>(
            yb, out_w + (size_t)i * DMODEL * DINNER, h, nullptr,
            BL, DMODEL, DINNER, DINNER, DINNER, DMODEL, 2);
    }

    layernorm_kernel<<<BL, 256>>>(h, ln_w, ln_b, lnb);

    // lm_head: out(2048,32000) = ln(2048,768) @ emb(32000,768)^T
    gemm_nt<<<dim3(VOCAB / 64, BL / 64), 256>>>(
        lnb, emb, out, nullptr,
        BL, VOCAB, DMODEL, DMODEL, DMODEL, VOCAB, 0);
}

// round 3
// speedup vs baseline: 1.6118x; 1.6118x over previous
#include <cuda_runtime.h>
#include <cuda_bf16.h>
#include <cstdint>
#include <math.h>

// ---------------- model constants ----------------
#define VOCAB   32000
#define DMODEL  768
#define NLAYERS 2
#define DSTATE  16
#define DCONV   4
#define DINNER  1536
#define DTRANK  48
#define BB      2
#define LL      1024
#define BL      (BB*LL)          // 2048 rows

// ---------------- scratch (device globals; no cudaMalloc allowed) ----------------
__device__ float g_h   [BL * DMODEL];        // residual stream
__device__ float g_xz  [BL * 2 * DINNER];    // in_proj output
__device__ float g_xc  [BL * DINNER];        // conv+silu output
__device__ float g_xdbl[BL * (DTRANK + 2*DSTATE)]; // 80 cols
__device__ float g_dt  [BL * DINNER];
__device__ float g_y   [BL * DINNER];
__device__ float g_ln  [BL * DMODEL];
__device__ float g_embt[VOCAB * DMODEL];     // tf32-rounded embedding

// ---------------- helpers ----------------
__device__ __forceinline__ float round_tf32(float x) {
    asm("cvt.rna.tf32.f32 %0, %0;" : "+f"(x));
    return x;
}

// ---------------- embedding gather ----------------
__global__ void embed_kernel(const int* __restrict__ x,
                             const float* __restrict__ emb,
                             float* __restrict__ h) {
    int idx = blockIdx.x * blockDim.x + threadIdx.x;   // over BL*DMODEL
    if (idx >= BL * DMODEL) return;
    int row = idx / DMODEL;
    int col = idx - row * DMODEL;
    h[idx] = emb[(size_t)x[row] * DMODEL + col];
}

// ---------------- round fp32 -> tf32 ----------------
__global__ void round_tf32_kernel(const float4* __restrict__ src,
                                  float4* __restrict__ dst, int n4) {
    int i = blockIdx.x * blockDim.x + threadIdx.x;
    if (i >= n4) return;
    float4 v = src[i];
    v.x = round_tf32(v.x); v.y = round_tf32(v.y);
    v.z = round_tf32(v.z); v.w = round_tf32(v.w);
    dst[i] = v;
}

// ---------------- tf32 tensor-core GEMM: C(MxN) = A(MxK) * B(NxK)^T ----------------
// A, B pre-rounded to tf32. M%128==0, N%128==0, K%32==0.
// 256 threads, 128x128x32 tile, warp tile 64x32, mma.m16n8k8, dynamic smem.
#define TBM 128
#define TBN 128
#define TBK 32
#define SPITCH 36   // floats; bank = (4*row + 8*ks + tig) % 32 -> conflict-free

#define AS(buf,row,col) smem[(buf) * (TBM*SPITCH) + (row) * SPITCH + (col)]
#define BS(buf,row,col) smem[BOFF + (buf) * (TBN*SPITCH) + (row) * SPITCH + (col)]
#define BOFF (2 * TBM * SPITCH)
#define SMEM_TF32_BYTES (4 * TBM * SPITCH * 4 * 2)   // 73728 bytes

__device__ __forceinline__ void cp_async16(unsigned saddr, const void* gaddr) {
    asm volatile("cp.async.ca.shared.global [%0], [%1], 16;\n"
                 :: "r"(saddr), "l"(gaddr));
}

__global__ __launch_bounds__(256) void gemm_tf32(
    const float* __restrict__ A, const float* __restrict__ B,
    float* __restrict__ C, int M, int N, int K)
{
    extern __shared__ float smem[];

    const int bm = blockIdx.x * TBM;
    const int bn = blockIdx.y * TBN;
    const int tid  = threadIdx.x;
    const int warp = tid >> 5;
    const int lane = tid & 31;
    const int wm = (warp & 1) * 64;   // warp origin in m
    const int wn = (warp >> 1) * 32;  // warp origin in n
    const int gid = lane >> 2;        // 0..7
    const int tig = lane & 3;         // 0..3

    // loader mapping: 256 threads cover 32 rows x 32 cols (float4), 4 row-waves
    const int lrow = tid >> 3;        // 0..31
    const int lcol = (tid & 7) * 4;   // 0,4,...,28

    const float* Ag = A + (size_t)(bm + lrow) * K + lcol;
    const float* Bg = B + (size_t)(bn + lrow) * K + lcol;

    float acc[4][4][4];
    #pragma unroll
    for (int i = 0; i < 4; i++)
        #pragma unroll
        for (int j = 0; j < 4; j++)
            #pragma unroll
            for (int r = 0; r < 4; r++) acc[i][j][r] = 0.f;

    unsigned sbase = (unsigned)__cvta_generic_to_shared(smem);
    const unsigned bufBytes = TBM * SPITCH * 4;
    const unsigned bOffB    = BOFF * 4;

    const int KT = K / TBK;

    // prologue: load tile 0
    {
        unsigned dA = sbase + (lrow * SPITCH + lcol) * 4;
        unsigned dB = sbase + bOffB + (lrow * SPITCH + lcol) * 4;
        #pragma unroll
        for (int r = 0; r < 4; r++) {
            cp_async16(dA + r * 32 * SPITCH * 4, Ag + (size_t)(32 * r) * K);
            cp_async16(dB + r * 32 * SPITCH * 4, Bg + (size_t)(32 * r) * K);
        }
        asm volatile("cp.async.commit_group;\n");
    }

    for (int kt = 0; kt < KT; kt++) {
        int cur = kt & 1;
        if (kt + 1 < KT) {
            int nxt = (kt + 1) & 1;
            int k0 = (kt + 1) * TBK;
            unsigned dA = sbase + nxt * bufBytes + (lrow * SPITCH + lcol) * 4;
            unsigned dB = sbase + bOffB + nxt * bufBytes + (lrow * SPITCH + lcol) * 4;
            #pragma unroll
            for (int r = 0; r < 4; r++) {
                cp_async16(dA + r * 32 * SPITCH * 4, Ag + (size_t)(32 * r) * K + k0);
                cp_async16(dB + r * 32 * SPITCH * 4, Bg + (size_t)(32 * r) * K + k0);
            }
            asm volatile("cp.async.commit_group;\n");
            asm volatile("cp.async.wait_group 1;\n");
        } else {
            asm volatile("cp.async.wait_group 0;\n");
        }
        __syncthreads();

        #pragma unroll
        for (int ks = 0; ks < 4; ks++) {
            unsigned a[4][4];
            #pragma unroll
            for (int mi = 0; mi < 4; mi++) {
                const float* p = &AS(cur, wm + 16 * mi + gid, ks * 8 + tig);
                a[mi][0] = __float_as_uint(p[0]);
                a[mi][1] = __float_as_uint(p[8 * SPITCH]);
                a[mi][2] = __float_as_uint(p[4]);
                a[mi][3] = __float_as_uint(p[8 * SPITCH + 4]);
            }
            unsigned b[4][2];
            #pragma unroll
            for (int nj = 0; nj < 4; nj++) {
                const float* q = &BS(cur, wn + 8 * nj + gid, ks * 8 + tig);
                b[nj][0] = __float_as_uint(q[0]);
                b[nj][1] = __float_as_uint(q[4]);
            }
            #pragma unroll
            for (int mi = 0; mi < 4; mi++)
                #pragma unroll
                for (int nj = 0; nj < 4; nj++) {
                    asm volatile(
                        "mma.sync.aligned.m16n8k8.row.col.f32.tf32.tf32.f32 "
                        "{%0,%1,%2,%3}, {%4,%5,%6,%7}, {%8,%9}, {%0,%1,%2,%3};\n"
                        : "+f"(acc[mi][nj][0]), "+f"(acc[mi][nj][1]),
                          "+f"(acc[mi][nj][2]), "+f"(acc[mi][nj][3])
                        : "r"(a[mi][0]), "r"(a[mi][1]), "r"(a[mi][2]), "r"(a[mi][3]),
                          "r"(b[nj][0]), "r"(b[nj][1]));
                }
        }
        __syncthreads();
    }

    // epilogue
    #pragma unroll
    for (int mi = 0; mi < 4; mi++) {
        int row = bm + wm + 16 * mi + gid;
        #pragma unroll
        for (int nj = 0; nj < 4; nj++) {
            int col = bn + wn + 8 * nj + 2 * tig;
            float2 v0 = make_float2(acc[mi][nj][0], acc[mi][nj][1]);
            float2 v1 = make_float2(acc[mi][nj][2], acc[mi][nj][3]);
            *(float2*)&C[(size_t)row * N + col]       = v0;
            *(float2*)&C[(size_t)(row + 8) * N + col] = v1;
        }
    }
}

// ---------------- generic fp32 GEMM: C(MxN) = A(MxK) * B(NxK)^T ----------------
// mode 0: store; mode 1: softplus(acc + bias[col]); mode 2: acc + C (residual)
__global__ __launch_bounds__(256) void gemm_nt(
    const float* __restrict__ A, const float* __restrict__ B,
    float* __restrict__ C, const float* __restrict__ bias,
    int M, int N, int K, int lda, int ldb, int ldc, int mode)
{
    __shared__ __align__(16) float As[16][68];
    __shared__ __align__(16) float Bs[16][68];
    const int bm = blockIdx.y * 64;
    const int bn = blockIdx.x * 64;
    const int tid = threadIdx.x;
    const int lrow = tid >> 2;          // 0..63
    const int lcol = (tid & 3) << 2;    // 0,4,8,12
    const int tr = (tid >> 4) << 2;     // 0..60
    const int tc = (tid & 15) << 2;     // 0..60

    float acc[4][4];
    #pragma unroll
    for (int i = 0; i < 4; i++)
        #pragma unroll
        for (int j = 0; j < 4; j++) acc[i][j] = 0.f;

    const bool bvalid = (bn + lrow) < N;
    const float* Aptr = A + (size_t)(bm + lrow) * lda + lcol;
    const float* Bptr = B + (size_t)(bn + lrow) * ldb + lcol;

    for (int k0 = 0; k0 < K; k0 += 16) {
        float4 av = *(const float4*)(Aptr + k0);
        float4 bv = make_float4(0.f, 0.f, 0.f, 0.f);
        if (bvalid) bv = *(const float4*)(Bptr + k0);
        As[lcol+0][lrow] = av.x; As[lcol+1][lrow] = av.y;
        As[lcol+2][lrow] = av.z; As[lcol+3][lrow] = av.w;
        Bs[lcol+0][lrow] = bv.x; Bs[lcol+1][lrow] = bv.y;
        Bs[lcol+2][lrow] = bv.z; Bs[lcol+3][lrow] = bv.w;
        __syncthreads();
        #pragma unroll
        for (int kk = 0; kk < 16; kk++) {
            float4 a = *(const float4*)&As[kk][tr];
            float4 b = *(const float4*)&Bs[kk][tc];
            acc[0][0] += a.x*b.x; acc[0][1] += a.x*b.y; acc[0][2] += a.x*b.z; acc[0][3] += a.x*b.w;
            acc[1][0] += a.y*b.x; acc[1][1] += a.y*b.y; acc[1][2] += a.y*b.z; acc[1][3] += a.y*b.w;
            acc[2][0] += a.z*b.x; acc[2][1] += a.z*b.y; acc[2][2] += a.z*b.z; acc[2][3] += a.z*b.w;
            acc[3][0] += a.w*b.x; acc[3][1] += a.w*b.y; acc[3][2] += a.w*b.z; acc[3][3] += a.w*b.w;
        }
        __syncthreads();
    }

    #pragma unroll
    for (int i = 0; i < 4; i++) {
        int row = bm + tr + i;
        #pragma unroll
        for (int j = 0; j < 4; j++) {
            int col = bn + tc + j;
            if (col < N) {
                float v = acc[i][j];
                if (mode == 1) {
                    v += bias[col];
                    v = (v > 20.f) ? v : log1pf(__expf(v));   // softplus
                } else if (mode == 2) {
                    v += C[(size_t)row * ldc + col];
                }
                C[(size_t)row * ldc + col] = v;
            }
        }
    }
}

// ---------------- depthwise causal conv (K=4) + SiLU ----------------
__global__ void conv_silu_kernel(const float* __restrict__ xz,
                                 const float* __restrict__ w,
                                 const float* __restrict__ b,
                                 float* __restrict__ xc)
{
    int idx = blockIdx.x * blockDim.x + threadIdx.x;
    if (idx >= BL * DINNER) return;
    int d  = idx % DINNER;
    int l  = (idx / DINNER) % LL;
    int bb = idx / (DINNER * LL);
    float s = b[d];
    #pragma unroll
    for (int k = 0; k < DCONV; k++) {
        int ll = l - (DCONV - 1) + k;
        if (ll >= 0)
            s += w[d * DCONV + k] * xz[(size_t)(bb * LL + ll) * (2 * DINNER) + d];
    }
    xc[idx] = s / (1.f + __expf(-s));   // silu
}

// ---------------- selective scan (one thread per (b, d) channel) ----------------
__global__ void scan_kernel(const float* __restrict__ xc,
                            const float* __restrict__ dt,
                            const float* __restrict__ xdbl,
                            const float* __restrict__ xz,
                            const float* __restrict__ A_log,
                            const float* __restrict__ Dp,
                            float* __restrict__ y)
{
    int c = blockIdx.x * blockDim.x + threadIdx.x;
    if (c >= BB * DINNER) return;
    int b = c / DINNER;
    int d = c - b * DINNER;

    float Av[DSTATE];
    #pragma unroll
    for (int n = 0; n < DSTATE; n++) Av[n] = -__expf(A_log[d * DSTATE + n]);
    const float Dv = Dp[d];

    float hs[DSTATE];
    #pragma unroll
    for (int n = 0; n < DSTATE; n++) hs[n] = 0.f;

    const float* dtp = dt + (size_t)b * LL * DINNER + d;
    const float* up  = xc + (size_t)b * LL * DINNER + d;
    const float* zp  = xz + (size_t)b * LL * (2 * DINNER) + DINNER + d;
    const float4* bc = (const float4*)xdbl + (size_t)b * LL * 20 + 12;
    float* yp = y + (size_t)b * LL * DINNER + d;

    for (int l = 0; l < LL; l++) {
        float dtv = dtp[(size_t)l * DINNER];
        float uv  = up [(size_t)l * DINNER];
        const float4* row = bc + (size_t)l * 20;
        float4 b0 = row[0], b1 = row[1], b2 = row[2], b3 = row[3];
        float4 c0 = row[4], c1 = row[5], c2 = row[6], c3 = row[7];
        float Bv[16] = {b0.x,b0.y,b0.z,b0.w, b1.x,b1.y,b1.z,b1.w,
                        b2.x,b2.y,b2.z,b2.w, b3.x,b3.y,b3.z,b3.w};
        float Cv[16] = {c0.x,c0.y,c0.z,c0.w, c1.x,c1.y,c1.z,c1.w,
                        c2.x,c2.y,c2.z,c2.w, c3.x,c3.y,c3.z,c3.w};
        float du = dtv * uv;
        float accv = 0.f;
        #pragma unroll
        for (int n = 0; n < DSTATE; n++) {
            float dA = __expf(dtv * Av[n]);
            hs[n] = dA * hs[n] + du * Bv[n];
            accv += hs[n] * Cv[n];
        }
        float zv = zp[(size_t)l * (2 * DINNER)];
        float silz = zv / (1.f + __expf(-zv));
        yp[(size_t)l * DINNER] = (accv + uv * Dv) * silz;
    }
}

// ---------------- layernorm (block per row), output rounded to tf32 ----------------
__global__ void layernorm_kernel(const float* __restrict__ x,
                                 const float* __restrict__ w,
                                 const float* __restrict__ b,
                                 float* __restrict__ out)
{
    __shared__ float red[32];
    int row = blockIdx.x;
    const float* xr = x + (size_t)row * DMODEL;
    float s = 0.f, s2 = 0.f;
    for (int i = threadIdx.x; i < DMODEL; i += blockDim.x) {
        float v = xr[i];
        s += v; s2 += v * v;
    }
    #pragma unroll
    for (int o = 16; o > 0; o >>= 1) {
        s  += __shfl_down_sync(0xffffffff, s,  o);
        s2 += __shfl_down_sync(0xffffffff, s2, o);
    }
    int lane = threadIdx.x & 31, wid = threadIdx.x >> 5;
    if (lane == 0) { red[wid] = s; red[wid + 16] = s2; }
    __syncthreads();
    if (wid == 0) {
        int nw = blockDim.x >> 5;
        s  = (lane < nw) ? red[lane]      : 0.f;
        s2 = (lane < nw) ? red[lane + 16] : 0.f;
        #pragma unroll
        for (int o = 16; o > 0; o >>= 1) {
            s  += __shfl_down_sync(0xffffffff, s,  o);
            s2 += __shfl_down_sync(0xffffffff, s2, o);
        }
        if (lane == 0) { red[0] = s; red[1] = s2; }
    }
    __syncthreads();
    float mu  = red[0] / DMODEL;
    float var = red[1] / DMODEL - mu * mu;
    float rstd = rsqrtf(var + 1e-5f);
    for (int i = threadIdx.x; i < DMODEL; i += blockDim.x) {
        float v = (xr[i] - mu) * rstd * w[i] + b[i];
        out[(size_t)row * DMODEL + i] = round_tf32(v);   // tf32-rounded for lm_head
    }
}

// ---------------- host launcher ----------------
extern "C" void kernel_launch(void* const* d_in, const int* in_sizes, int n_in,
                              void* d_out, int out_size)
{
    const int*   x      = (const int*)  d_in[0];
    const float* emb    = (const float*)d_in[1];
    const float* in_w   = (const float*)d_in[2];   // (2, 3072, 768)
    const float* conv_w = (const float*)d_in[3];   // (2, 1536, 4)
    const float* conv_b = (const float*)d_in[4];   // (2, 1536)
    const float* xp_w   = (const float*)d_in[5];   // (2, 80, 1536)
    const float* dt_w   = (const float*)d_in[6];   // (2, 1536, 48)
    const float* dt_b   = (const float*)d_in[7];   // (2, 1536)
    const float* A_log  = (const float*)d_in[8];   // (2, 1536, 16)
    const float* Dp     = (const float*)d_in[9];   // (2, 1536)
    const float* out_w  = (const float*)d_in[10];  // (2, 768, 1536)
    const float* ln_w   = (const float*)d_in[11];
    const float* ln_b   = (const float*)d_in[12];
    float* out = (float*)d_out;

    float *h, *xz, *xc, *xdbl, *dtb, *yb, *lnb, *embt;
    cudaGetSymbolAddress((void**)&h,    g_h);
    cudaGetSymbolAddress((void**)&xz,   g_xz);
    cudaGetSymbolAddress((void**)&xc,   g_xc);
    cudaGetSymbolAddress((void**)&xdbl, g_xdbl);
    cudaGetSymbolAddress((void**)&dtb,  g_dt);
    cudaGetSymbolAddress((void**)&yb,   g_y);
    cudaGetSymbolAddress((void**)&lnb,  g_ln);
    cudaGetSymbolAddress((void**)&embt, g_embt);

    // allow >48KB dynamic smem for the tf32 GEMM (host-state, capture-safe)
    cudaFuncSetAttribute(gemm_tf32, cudaFuncAttributeMaxDynamicSharedMemorySize,
                         SMEM_TF32_BYTES);

    embed_kernel<<<(BL * DMODEL + 255) / 256, 256>>>(x, emb, h);

    // round embedding to tf32 once per launch (for lm_head B operand)
    {
        int n4 = VOCAB * DMODEL / 4;
        round_tf32_kernel<<<(n4 + 255) / 256, 256>>>((const float4*)emb,
                                                     (float4*)embt, n4);
    }

    for (int i = 0; i < NLAYERS; i++) {
        gemm_nt<<<dim3(2 * DINNER / 64, BL / 64), 256>>>(
            h, in_w + (size_t)i * 2 * DINNER * DMODEL, xz, nullptr,
            BL, 2 * DINNER, DMODEL, DMODEL, DMODEL, 2 * DINNER, 0);

        conv_silu_kernel<<<(BL * DINNER + 255) / 256, 256>>>(
            xz, conv_w + (size_t)i * DINNER * DCONV, conv_b + (size_t)i * DINNER, xc);

        gemm_nt<<<dim3(2, BL / 64), 256>>>(
            xc, xp_w + (size_t)i * (DTRANK + 2 * DSTATE) * DINNER, xdbl, nullptr,
            BL, DTRANK + 2 * DSTATE, DINNER, DINNER, DINNER, DTRANK + 2 * DSTATE, 0);

        gemm_nt<<<dim3(DINNER / 64, BL / 64), 256>>>(
            xdbl, dt_w + (size_t)i * DINNER * DTRANK, dtb, dt_b + (size_t)i * DINNER,
            BL, DINNER, DTRANK, DTRANK + 2 * DSTATE, DTRANK, DINNER, 1);

        scan_kernel<<<(BB * DINNER + 255) / 256, 256>>>(
            xc, dtb, xdbl, xz, A_log + (size_t)i * DINNER * DSTATE,
            Dp + (size_t)i * DINNER, yb);

        gemm_nt<<<dim3(DMODEL / 64, BL / 64), 256>>>(
            yb, out_w + (size_t)i * DMODEL * DINNER, h, nullptr,
            BL, DMODEL, DINNER, DINNER, DINNER, DMODEL, 2);
    }

    layernorm_kernel<<<BL, 256>>>(h, ln_w, ln_b, lnb);

    // lm_head on tensor cores: out(2048,32000) = lnb_tf32 @ embt^T
    gemm_tf32<<<dim3(BL / TBM, VOCAB / TBN), 256, SMEM_TF32_BYTES>>>(
        lnb, embt, out, BL, VOCAB, DMODEL);
}

// round 4
// speedup vs baseline: 2.0302x; 1.2596x over previous
#include <cuda_runtime.h>
#include <cuda_bf16.h>
#include <cstdint>
#include <math.h>

// ---------------- model constants ----------------
#define VOCAB   32000
#define DMODEL  768
#define NLAYERS 2
#define DSTATE  16
#define DCONV   4
#define DINNER  1536
#define DTRANK  48
#define BB      2
#define LL      1024
#define BL      (BB*LL)          // 2048 rows

// ---------------- scratch (device globals; no cudaMalloc allowed) ----------------
__device__ float g_h   [BL * DMODEL];        // residual stream (fp32 exact)
__device__ float g_xz  [BL * 2 * DINNER];    // in_proj output
__device__ float g_xc  [BL * DINNER];        // conv+silu output
__device__ float g_xdbl[BL * (DTRANK + 2*DSTATE)]; // 80 cols
__device__ float g_dt  [BL * DINNER];
__device__ float g_y   [BL * DINNER];        // scan output, tf32-rounded
__device__ float g_ln  [BL * DMODEL];        // rounded-h scratch during layers; ln output at end
__device__ float g_embt[VOCAB * DMODEL];     // tf32-rounded embedding
__device__ float g_inwt[NLAYERS * 2 * DINNER * DMODEL];  // tf32-rounded in_proj_w
__device__ float g_outwt[NLAYERS * DMODEL * DINNER];     // tf32-rounded out_proj_w

// ---------------- helpers ----------------
__device__ __forceinline__ float round_tf32(float x) {
    asm("cvt.rna.tf32.f32 %0, %0;" : "+f"(x));
    return x;
}

// ---------------- embedding gather ----------------
__global__ void embed_kernel(const int* __restrict__ x,
                             const float* __restrict__ emb,
                             float* __restrict__ h) {
    int idx = blockIdx.x * blockDim.x + threadIdx.x;   // over BL*DMODEL
    if (idx >= BL * DMODEL) return;
    int row = idx / DMODEL;
    int col = idx - row * DMODEL;
    h[idx] = emb[(size_t)x[row] * DMODEL + col];
}

// ---------------- round fp32 -> tf32 ----------------
__global__ void round_tf32_kernel(const float4* __restrict__ src,
                                  float4* __restrict__ dst, int n4) {
    int i = blockIdx.x * blockDim.x + threadIdx.x;
    if (i >= n4) return;
    float4 v = src[i];
    v.x = round_tf32(v.x); v.y = round_tf32(v.y);
    v.z = round_tf32(v.z); v.w = round_tf32(v.w);
    dst[i] = v;
}

// ---------------- tf32 tensor-core GEMM: C(MxN) = A(MxK) * B(NxK)^T ----------------
// A, B pre-rounded to tf32. M%128==0, N%128==0, K%32==0.
// mode 0: store; mode 2: C += acc (residual).
// 256 threads, 128x128x32 tile, warp tile 64x32, mma.m16n8k8, dynamic smem, 2 CTA/SM.
#define TBM 128
#define TBN 128
#define TBK 32
#define SPITCH 36   // floats; bank = (4*row + tig) % 32 -> conflict-free

#define AS(buf,row,col) smem[(buf) * (TBM*SPITCH) + (row) * SPITCH + (col)]
#define BS(buf,row,col) smem[BOFF + (buf) * (TBN*SPITCH) + (row) * SPITCH + (col)]
#define BOFF (2 * TBM * SPITCH)
#define SMEM_TF32_BYTES (4 * TBM * SPITCH * 4 * 2)   // 73728 bytes

__device__ __forceinline__ void cp_async16(unsigned saddr, const void* gaddr) {
    asm volatile("cp.async.ca.shared.global [%0], [%1], 16;\n"
                 :: "r"(saddr), "l"(gaddr));
}

__global__ __launch_bounds__(256, 2) void gemm_tf32(
    const float* __restrict__ A, const float* __restrict__ B,
    float* __restrict__ C, int M, int N, int K, int mode)
{
    extern __shared__ float smem[];

    const int bm = blockIdx.x * TBM;
    const int bn = blockIdx.y * TBN;
    const int tid  = threadIdx.x;
    const int warp = tid >> 5;
    const int lane = tid & 31;
    const int wm = (warp & 1) * 64;   // warp origin in m
    const int wn = (warp >> 1) * 32;  // warp origin in n
    const int gid = lane >> 2;        // 0..7
    const int tig = lane & 3;         // 0..3

    // loader mapping: 256 threads cover 32 rows x 32 cols (float4), 4 row-waves
    const int lrow = tid >> 3;        // 0..31
    const int lcol = (tid & 7) * 4;   // 0,4,...,28

    const float* Ag = A + (size_t)(bm + lrow) * K + lcol;
    const float* Bg = B + (size_t)(bn + lrow) * K + lcol;

    float acc[4][4][4];
    #pragma unroll
    for (int i = 0; i < 4; i++)
        #pragma unroll
        for (int j = 0; j < 4; j++)
            #pragma unroll
            for (int r = 0; r < 4; r++) acc[i][j][r] = 0.f;

    unsigned sbase = (unsigned)__cvta_generic_to_shared(smem);
    const unsigned bufBytes = TBM * SPITCH * 4;
    const unsigned bOffB    = BOFF * 4;

    const int KT = K / TBK;

    // prologue: load tile 0
    {
        unsigned dA = sbase + (lrow * SPITCH + lcol) * 4;
        unsigned dB = sbase + bOffB + (lrow * SPITCH + lcol) * 4;
        #pragma unroll
        for (int r = 0; r < 4; r++) {
            cp_async16(dA + r * 32 * SPITCH * 4, Ag + (size_t)(32 * r) * K);
            cp_async16(dB + r * 32 * SPITCH * 4, Bg + (size_t)(32 * r) * K);
        }
        asm volatile("cp.async.commit_group;\n");
    }

    for (int kt = 0; kt < KT; kt++) {
        int cur = kt & 1;
        if (kt + 1 < KT) {
            int nxt = (kt + 1) & 1;
            int k0 = (kt + 1) * TBK;
            unsigned dA = sbase + nxt * bufBytes + (lrow * SPITCH + lcol) * 4;
            unsigned dB = sbase + bOffB + nxt * bufBytes + (lrow * SPITCH + lcol) * 4;
            #pragma unroll
            for (int r = 0; r < 4; r++) {
                cp_async16(dA + r * 32 * SPITCH * 4, Ag + (size_t)(32 * r) * K + k0);
                cp_async16(dB + r * 32 * SPITCH * 4, Bg + (size_t)(32 * r) * K + k0);
            }
            asm volatile("cp.async.commit_group;\n");
            asm volatile("cp.async.wait_group 1;\n");
        } else {
            asm volatile("cp.async.wait_group 0;\n");
        }
        __syncthreads();

        #pragma unroll
        for (int ks = 0; ks < 4; ks++) {
            unsigned a[4][4];
            #pragma unroll
            for (int mi = 0; mi < 4; mi++) {
                const float* p = &AS(cur, wm + 16 * mi + gid, ks * 8 + tig);
                a[mi][0] = __float_as_uint(p[0]);
                a[mi][1] = __float_as_uint(p[8 * SPITCH]);
                a[mi][2] = __float_as_uint(p[4]);
                a[mi][3] = __float_as_uint(p[8 * SPITCH + 4]);
            }
            unsigned b[4][2];
            #pragma unroll
            for (int nj = 0; nj < 4; nj++) {
                const float* q = &BS(cur, wn + 8 * nj + gid, ks * 8 + tig);
                b[nj][0] = __float_as_uint(q[0]);
                b[nj][1] = __float_as_uint(q[4]);
            }
            #pragma unroll
            for (int mi = 0; mi < 4; mi++)
                #pragma unroll
                for (int nj = 0; nj < 4; nj++) {
                    asm volatile(
                        "mma.sync.aligned.m16n8k8.row.col.f32.tf32.tf32.f32 "
                        "{%0,%1,%2,%3}, {%4,%5,%6,%7}, {%8,%9}, {%0,%1,%2,%3};\n"
                        : "+f"(acc[mi][nj][0]), "+f"(acc[mi][nj][1]),
                          "+f"(acc[mi][nj][2]), "+f"(acc[mi][nj][3])
                        : "r"(a[mi][0]), "r"(a[mi][1]), "r"(a[mi][2]), "r"(a[mi][3]),
                          "r"(b[nj][0]), "r"(b[nj][1]));
                }
        }
        __syncthreads();
    }

    // epilogue
    #pragma unroll
    for (int mi = 0; mi < 4; mi++) {
        int row = bm + wm + 16 * mi + gid;
        #pragma unroll
        for (int nj = 0; nj < 4; nj++) {
            int col = bn + wn + 8 * nj + 2 * tig;
            float2 v0 = make_float2(acc[mi][nj][0], acc[mi][nj][1]);
            float2 v1 = make_float2(acc[mi][nj][2], acc[mi][nj][3]);
            float* c0 = &C[(size_t)row * N + col];
            float* c1 = &C[(size_t)(row + 8) * N + col];
            if (mode == 2) {
                float2 o0 = *(float2*)c0, o1 = *(float2*)c1;
                v0.x += o0.x; v0.y += o0.y;
                v1.x += o1.x; v1.y += o1.y;
            }
            *(float2*)c0 = v0;
            *(float2*)c1 = v1;
        }
    }
}

// ---------------- generic fp32 GEMM (small N): C(MxN) = A(MxK) * B(NxK)^T ----------------
// mode 0: store; mode 1: softplus(acc + bias[col])
__global__ __launch_bounds__(256) void gemm_nt(
    const float* __restrict__ A, const float* __restrict__ B,
    float* __restrict__ C, const float* __restrict__ bias,
    int M, int N, int K, int lda, int ldb, int ldc, int mode)
{
    __shared__ __align__(16) float As[16][68];
    __shared__ __align__(16) float Bs[16][68];
    const int bm = blockIdx.y * 64;
    const int bn = blockIdx.x * 64;
    const int tid = threadIdx.x;
    const int lrow = tid >> 2;          // 0..63
    const int lcol = (tid & 3) << 2;    // 0,4,8,12
    const int tr = (tid >> 4) << 2;     // 0..60
    const int tc = (tid & 15) << 2;     // 0..60

    float acc[4][4];
    #pragma unroll
    for (int i = 0; i < 4; i++)
        #pragma unroll
        for (int j = 0; j < 4; j++) acc[i][j] = 0.f;

    const bool bvalid = (bn + lrow) < N;
    const float* Aptr = A + (size_t)(bm + lrow) * lda + lcol;
    const float* Bptr = B + (size_t)(bn + lrow) * ldb + lcol;

    for (int k0 = 0; k0 < K; k0 += 16) {
        float4 av = *(const float4*)(Aptr + k0);
        float4 bv = make_float4(0.f, 0.f, 0.f, 0.f);
        if (bvalid) bv = *(const float4*)(Bptr + k0);
        As[lcol+0][lrow] = av.x; As[lcol+1][lrow] = av.y;
        As[lcol+2][lrow] = av.z; As[lcol+3][lrow] = av.w;
        Bs[lcol+0][lrow] = bv.x; Bs[lcol+1][lrow] = bv.y;
        Bs[lcol+2][lrow] = bv.z; Bs[lcol+3][lrow] = bv.w;
        __syncthreads();
        #pragma unroll
        for (int kk = 0; kk < 16; kk++) {
            float4 a = *(const float4*)&As[kk][tr];
            float4 b = *(const float4*)&Bs[kk][tc];
            acc[0][0] += a.x*b.x; acc[0][1] += a.x*b.y; acc[0][2] += a.x*b.z; acc[0][3] += a.x*b.w;
            acc[1][0] += a.y*b.x; acc[1][1] += a.y*b.y; acc[1][2] += a.y*b.z; acc[1][3] += a.y*b.w;
            acc[2][0] += a.z*b.x; acc[2][1] += a.z*b.y; acc[2][2] += a.z*b.z; acc[2][3] += a.z*b.w;
            acc[3][0] += a.w*b.x; acc[3][1] += a.w*b.y; acc[3][2] += a.w*b.z; acc[3][3] += a.w*b.w;
        }
        __syncthreads();
    }

    #pragma unroll
    for (int i = 0; i < 4; i++) {
        int row = bm + tr + i;
        #pragma unroll
        for (int j = 0; j < 4; j++) {
            int col = bn + tc + j;
            if (col < N) {
                float v = acc[i][j];
                if (mode == 1) {
                    v += bias[col];
                    v = (v > 20.f) ? v : log1pf(__expf(v));   // softplus
                }
                C[(size_t)row * ldc + col] = v;
            }
        }
    }
}

// ---------------- depthwise causal conv (K=4) + SiLU ----------------
__global__ void conv_silu_kernel(const float* __restrict__ xz,
                                 const float* __restrict__ w,
                                 const float* __restrict__ b,
                                 float* __restrict__ xc)
{
    int idx = blockIdx.x * blockDim.x + threadIdx.x;
    if (idx >= BL * DINNER) return;
    int d  = idx % DINNER;
    int l  = (idx / DINNER) % LL;
    int bb = idx / (DINNER * LL);
    float s = b[d];
    #pragma unroll
    for (int k = 0; k < DCONV; k++) {
        int ll = l - (DCONV - 1) + k;
        if (ll >= 0)
            s += w[d * DCONV + k] * xz[(size_t)(bb * LL + ll) * (2 * DINNER) + d];
    }
    xc[idx] = s / (1.f + __expf(-s));   // silu
}

// ---------------- selective scan (one thread per (b, d) channel) ----------------
// output y is tf32-rounded (feeds tf32 out_proj)
__global__ void scan_kernel(const float* __restrict__ xc,
                            const float* __restrict__ dt,
                            const float* __restrict__ xdbl,
                            const float* __restrict__ xz,
                            const float* __restrict__ A_log,
                            const float* __restrict__ Dp,
                            float* __restrict__ y)
{
    int c = blockIdx.x * blockDim.x + threadIdx.x;
    if (c >= BB * DINNER) return;
    int b = c / DINNER;
    int d = c - b * DINNER;

    float Av[DSTATE];
    #pragma unroll
    for (int n = 0; n < DSTATE; n++) Av[n] = -__expf(A_log[d * DSTATE + n]);
    const float Dv = Dp[d];

    float hs[DSTATE];
    #pragma unroll
    for (int n = 0; n < DSTATE; n++) hs[n] = 0.f;

    const float* dtp = dt + (size_t)b * LL * DINNER + d;
    const float* up  = xc + (size_t)b * LL * DINNER + d;
    const float* zp  = xz + (size_t)b * LL * (2 * DINNER) + DINNER + d;
    const float4* bc = (const float4*)xdbl + (size_t)b * LL * 20 + 12;
    float* yp = y + (size_t)b * LL * DINNER + d;

    for (int l = 0; l < LL; l++) {
        float dtv = dtp[(size_t)l * DINNER];
        float uv  = up [(size_t)l * DINNER];
        const float4* row = bc + (size_t)l * 20;
        float4 b0 = row[0], b1 = row[1], b2 = row[2], b3 = row[3];
        float4 c0 = row[4], c1 = row[5], c2 = row[6], c3 = row[7];
        float Bv[16] = {b0.x,b0.y,b0.z,b0.w, b1.x,b1.y,b1.z,b1.w,
                        b2.x,b2.y,b2.z,b2.w, b3.x,b3.y,b3.z,b3.w};
        float Cv[16] = {c0.x,c0.y,c0.z,c0.w, c1.x,c1.y,c1.z,c1.w,
                        c2.x,c2.y,c2.z,c2.w, c3.x,c3.y,c3.z,c3.w};
        float du = dtv * uv;
        float accv = 0.f;
        #pragma unroll
        for (int n = 0; n < DSTATE; n++) {
            float dA = __expf(dtv * Av[n]);
            hs[n] = dA * hs[n] + du * Bv[n];
            accv += hs[n] * Cv[n];
        }
        float zv = zp[(size_t)l * (2 * DINNER)];
        float silz = zv / (1.f + __expf(-zv));
        yp[(size_t)l * DINNER] = round_tf32((accv + uv * Dv) * silz);
    }
}

// ---------------- layernorm (block per row), output rounded to tf32 ----------------
__global__ void layernorm_kernel(const float* __restrict__ x,
                                 const float* __restrict__ w,
                                 const float* __restrict__ b,
                                 float* __restrict__ out)
{
    __shared__ float red[32];
    int row = blockIdx.x;
    const float* xr = x + (size_t)row * DMODEL;
    float s = 0.f, s2 = 0.f;
    for (int i = threadIdx.x; i < DMODEL; i += blockDim.x) {
        float v = xr[i];
        s += v; s2 += v * v;
    }
    #pragma unroll
    for (int o = 16; o > 0; o >>= 1) {
        s  += __shfl_down_sync(0xffffffff, s,  o);
        s2 += __shfl_down_sync(0xffffffff, s2, o);
    }
    int lane = threadIdx.x & 31, wid = threadIdx.x >> 5;
    if (lane == 0) { red[wid] = s; red[wid + 16] = s2; }
    __syncthreads();
    if (wid == 0) {
        int nw = blockDim.x >> 5;
        s  = (lane < nw) ? red[lane]      : 0.f;
        s2 = (lane < nw) ? red[lane + 16] : 0.f;
        #pragma unroll
        for (int o = 16; o > 0; o >>= 1) {
            s  += __shfl_down_sync(0xffffffff, s,  o);
            s2 += __shfl_down_sync(0xffffffff, s2, o);
        }
        if (lane == 0) { red[0] = s; red[1] = s2; }
    }
    __syncthreads();
    float mu  = red[0] / DMODEL;
    float var = red[1] / DMODEL - mu * mu;
    float rstd = rsqrtf(var + 1e-5f);
    for (int i = threadIdx.x; i < DMODEL; i += blockDim.x) {
        float v = (xr[i] - mu) * rstd * w[i] + b[i];
        out[(size_t)row * DMODEL + i] = round_tf32(v);   // tf32-rounded for lm_head
    }
}

// ---------------- host launcher ----------------
extern "C" void kernel_launch(void* const* d_in, const int* in_sizes, int n_in,
                              void* d_out, int out_size)
{
    const int*   x      = (const int*)  d_in[0];
    const float* emb    = (const float*)d_in[1];
    const float* in_w   = (const float*)d_in[2];   // (2, 3072, 768)
    const float* conv_w = (const float*)d_in[3];   // (2, 1536, 4)
    const float* conv_b = (const float*)d_in[4];   // (2, 1536)
    const float* xp_w   = (const float*)d_in[5];   // (2, 80, 1536)
    const float* dt_w   = (const float*)d_in[6];   // (2, 1536, 48)
    const float* dt_b   = (const float*)d_in[7];   // (2, 1536)
    const float* A_log  = (const float*)d_in[8];   // (2, 1536, 16)
    const float* Dp     = (const float*)d_in[9];   // (2, 1536)
    const float* out_w  = (const float*)d_in[10];  // (2, 768, 1536)
    const float* ln_w   = (const float*)d_in[11];
    const float* ln_b   = (const float*)d_in[12];
    float* out = (float*)d_out;

    float *h, *xz, *xc, *xdbl, *dtb, *yb, *lnb, *embt, *inwt, *outwt;
    cudaGetSymbolAddress((void**)&h,     g_h);
    cudaGetSymbolAddress((void**)&xz,    g_xz);
    cudaGetSymbolAddress((void**)&xc,    g_xc);
    cudaGetSymbolAddress((void**)&xdbl,  g_xdbl);
    cudaGetSymbolAddress((void**)&dtb,   g_dt);
    cudaGetSymbolAddress((void**)&yb,    g_y);
    cudaGetSymbolAddress((void**)&lnb,   g_ln);
    cudaGetSymbolAddress((void**)&embt,  g_embt);
    cudaGetSymbolAddress((void**)&inwt,  g_inwt);
    cudaGetSymbolAddress((void**)&outwt, g_outwt);

    // allow >48KB dynamic smem for the tf32 GEMM (host-state, capture-safe)
    cudaFuncSetAttribute(gemm_tf32, cudaFuncAttributeMaxDynamicSharedMemorySize,
                         SMEM_TF32_BYTES);

    embed_kernel<<<(BL * DMODEL + 255) / 256, 256>>>(x, emb, h);

    // round weights/embedding to tf32 once per launch
    round_tf32_kernel<<<(VOCAB * DMODEL / 4 + 255) / 256, 256>>>(
        (const float4*)emb, (float4*)embt, VOCAB * DMODEL / 4);
    round_tf32_kernel<<<(NLAYERS * 2 * DINNER * DMODEL / 4 + 255) / 256, 256>>>(
        (const float4*)in_w, (float4*)inwt, NLAYERS * 2 * DINNER * DMODEL / 4);
    round_tf32_kernel<<<(NLAYERS * DMODEL * DINNER / 4 + 255) / 256, 256>>>(
        (const float4*)out_w, (float4*)outwt, NLAYERS * DMODEL * DINNER / 4);

    for (int i = 0; i < NLAYERS; i++) {
        // rounded copy of h for tf32 in_proj (g_ln reused as scratch)
        round_tf32_kernel<<<(BL * DMODEL / 4 + 255) / 256, 256>>>(
            (const float4*)h, (float4*)lnb, BL * DMODEL / 4);

        // in_proj: xz(2048,3072) = h_t32 @ in_w_t32^T  (tensor cores)
        gemm_tf32<<<dim3(BL / TBM, 2 * DINNER / TBN), 256, SMEM_TF32_BYTES>>>(
            lnb, inwt + (size_t)i * 2 * DINNER * DMODEL, xz,
            BL, 2 * DINNER, DMODEL, 0);

        conv_silu_kernel<<<(BL * DINNER + 255) / 256, 256>>>(
            xz, conv_w + (size_t)i * DINNER * DCONV, conv_b + (size_t)i * DINNER, xc);

        gemm_nt<<<dim3(2, BL / 64), 256>>>(
            xc, xp_w + (size_t)i * (DTRANK + 2 * DSTATE) * DINNER, xdbl, nullptr,
            BL, DTRANK + 2 * DSTATE, DINNER, DINNER, DINNER, DTRANK + 2 * DSTATE, 0);

        gemm_nt<<<dim3(DINNER / 64, BL / 64), 256>>>(
            xdbl, dt_w + (size_t)i * DINNER * DTRANK, dtb, dt_b + (size_t)i * DINNER,
            BL, DINNER, DTRANK, DTRANK + 2 * DSTATE, DTRANK, DINNER, 1);

        scan_kernel<<<(BB * DINNER + 255) / 256, 256>>>(
            xc, dtb, xdbl, xz, A_log + (size_t)i * DINNER * DSTATE,
            Dp + (size_t)i * DINNER, yb);

        // out_proj + residual: h += y_t32 @ out_w_t32^T  (tensor cores, mode 2)
        gemm_tf32<<<dim3(BL / TBM, DMODEL / TBN), 256, SMEM_TF32_BYTES>>>(
            yb, outwt + (size_t)i * DMODEL * DINNER, h,
            BL, DMODEL, DINNER, 2);
    }

    layernorm_kernel<<<BL, 256>>>(h, ln_w, ln_b, lnb);

    // lm_head on tensor cores: out(2048,32000) = lnb_t32 @ embt^T
    gemm_tf32<<<dim3(BL / TBM, VOCAB / TBN), 256, SMEM_TF32_BYTES>>>(
        lnb, embt, out, BL, VOCAB, DMODEL, 0);
}

// round 7
// speedup vs baseline: 2.3513x; 1.1582x over previous
#include <cuda_runtime.h>
#include <cuda_fp16.h>
#include <cstdint>
#include <math.h>

// ---------------- model constants ----------------
#define VOCAB   32000
#define DMODEL  768
#define NLAYERS 2
#define DSTATE  16
#define DCONV   4
#define DINNER  1536
#define DTRANK  48
#define BB      2
#define LL      1024
#define BL      (BB*LL)          // 2048 rows
#define XDLD    128              // padded xdbl row stride (floats)

// ---------------- scratch (device globals; no cudaMalloc allowed) ----------------
__device__ float g_h   [BL * DMODEL];        // residual stream (fp32)
__device__ float g_xz  [BL * 2 * DINNER];
__device__ float g_xc  [BL * DINNER];        // conv+silu fp32 (scan input u)
__device__ float g_xdbl[BL * XDLD];          // x_proj out, padded to 128 cols
__device__ float g_dt  [BL * DINNER];
__device__ __half g_yh  [BL * DINNER];       // scan output (fp16, feeds out_proj)
__device__ __half g_lnh [BL * DMODEL];       // layernorm output (fp16, feeds lm_head)
__device__ __half g_hh  [BL * DMODEL];       // fp16 copy of h (feeds in_proj)
__device__ __half g_xch [BL * DINNER];       // fp16 copy of xc (feeds x_proj)
__device__ __half g_embh[VOCAB * DMODEL];    // fp16 embedding
__device__ __half g_inwh[NLAYERS * 2 * DINNER * DMODEL];
__device__ __half g_outwh[NLAYERS * DMODEL * DINNER];
__device__ __half g_xpwh[NLAYERS * 128 * DINNER];   // xp_w zero-padded 80->128 rows

// ---------------- embedding gather ----------------
__global__ void embed_kernel(const int* __restrict__ x,
                             const float* __restrict__ emb,
                             float* __restrict__ h) {
    int idx = blockIdx.x * blockDim.x + threadIdx.x;
    if (idx >= BL * DMODEL) return;
    int row = idx / DMODEL;
    int col = idx - row * DMODEL;
    h[idx] = emb[(size_t)x[row] * DMODEL + col];
}

// ---------------- fp32 -> fp16 convert (4 elems/thread) ----------------
__global__ void cvt_f16_kernel(const float4* __restrict__ src,
                               uint2* __restrict__ dst, int n4) {
    int i = blockIdx.x * blockDim.x + threadIdx.x;
    if (i >= n4) return;
    float4 v = src[i];
    __half2 h01 = __float22half2_rn(make_float2(v.x, v.y));
    __half2 h23 = __float22half2_rn(make_float2(v.z, v.w));
    uint2 o;
    o.x = *(unsigned*)&h01;
    o.y = *(unsigned*)&h23;
    dst[i] = o;
}

// ---------------- xp_w fp16 pad kernel: (80,1536) -> (128,1536) rows, zero pad ----------------
__global__ void xpw_pad_kernel(const float* __restrict__ src,
                               __half* __restrict__ dst) {
    int idx = blockIdx.x * blockDim.x + threadIdx.x;   // over NLAYERS*128*DINNER
    if (idx >= NLAYERS * 128 * DINNER) return;
    int layer = idx / (128 * DINNER);
    int rem   = idx - layer * 128 * DINNER;
    int row   = rem / DINNER;
    int col   = rem - row * DINNER;
    float v = 0.f;
    if (row < DTRANK + 2 * DSTATE)
        v = src[(size_t)layer * (DTRANK + 2 * DSTATE) * DINNER + row * DINNER + col];
    dst[idx] = __float2half_rn(v);
}

// ---------------- fp16 tensor-core GEMM: C(MxN) = A(MxK) * B(NxK)^T ----------------
// mode 0: store; mode 2: C += acc (residual).
// 256 threads, 128x128x32 tile, warp tile 64x32, mma.m16n8k16.f16, 2 CTA/SM.
#define FTM 128
#define FTN 128
#define FTK 32      // halves per K tile
#define FP  40      // smem pitch in halves (banks = row*20+tig, conflict-free)
#define FBUF (128 * FP)           // halves per buffer
#define FBUF_B (FBUF * 2)         // bytes per buffer

__device__ __forceinline__ void cp_async16(unsigned saddr, const void* gaddr) {
    asm volatile("cp.async.ca.shared.global [%0], [%1], 16;\n"
                 :: "r"(saddr), "l"(gaddr));
}

__global__ __launch_bounds__(256, 2) void gemm_f16(
    const __half* __restrict__ A, const __half* __restrict__ B,
    float* __restrict__ C, int M, int N, int K, int mode)
{
    __shared__ __align__(16) __half As[2][FBUF];
    __shared__ __align__(16) __half Bs[2][FBUF];

    const int bm = blockIdx.x * FTM;
    const int bn = blockIdx.y * FTN;
    const int tid  = threadIdx.x;
    const int warp = tid >> 5;
    const int lane = tid & 31;
    const int wm = (warp & 1) * 64;
    const int wn = (warp >> 1) * 32;
    const int gid = lane >> 2;        // 0..7
    const int tig = lane & 3;         // 0..3

    // loader: 256 threads x 16B = 4KB/pass; one 128x32h tile = 8KB -> 2 passes
    const int lrow = tid >> 2;        // 0..63
    const int lcb  = (tid & 3) * 16;  // byte col within 64B row

    float acc[4][4][4];
    #pragma unroll
    for (int i = 0; i < 4; i++)
        #pragma unroll
        for (int j = 0; j < 4; j++)
            #pragma unroll
            for (int r = 0; r < 4; r++) acc[i][j][r] = 0.f;

    unsigned sA = (unsigned)__cvta_generic_to_shared(&As[0][0]);
    unsigned sB = (unsigned)__cvta_generic_to_shared(&Bs[0][0]);
    const int KT = K / FTK;

    // prologue: tile 0
    {
        #pragma unroll
        for (int p = 0; p < 2; p++) {
            int row = lrow + 64 * p;
            unsigned soff = (unsigned)(row * FP * 2 + lcb);
            cp_async16(sA + soff, (const char*)(A + (size_t)(bm + row) * K) + lcb);
            cp_async16(sB + soff, (const char*)(B + (size_t)(bn + row) * K) + lcb);
        }
        asm volatile("cp.async.commit_group;\n");
    }

    for (int kt = 0; kt < KT; kt++) {
        int cur = kt & 1;
        if (kt + 1 < KT) {
            int nxt = (kt + 1) & 1;
            const char* kadd = (const char*)((size_t)(kt + 1) * FTK * 2);
            #pragma unroll
            for (int p = 0; p < 2; p++) {
                int row = lrow + 64 * p;
                unsigned soff = (unsigned)(nxt * FBUF_B + row * FP * 2 + lcb);
                cp_async16(sA + soff,
                           (const char*)(A + (size_t)(bm + row) * K) + (size_t)kadd + lcb);
                cp_async16(sB + soff,
                           (const char*)(B + (size_t)(bn + row) * K) + (size_t)kadd + lcb);
            }
            asm volatile("cp.async.commit_group;\n");
            asm volatile("cp.async.wait_group 1;\n");
        } else {
            asm volatile("cp.async.wait_group 0;\n");
        }
        __syncthreads();

        #pragma unroll
        for (int ks = 0; ks < 2; ks++) {
            const int kh = ks * 16;
            unsigned a[4][4];
            #pragma unroll
            for (int mi = 0; mi < 4; mi++) {
                const __half* p0 = &As[cur][(wm + 16 * mi + gid) * FP + kh + 2 * tig];
                a[mi][0] = *(const unsigned*)(p0);
                a[mi][1] = *(const unsigned*)(p0 + 8 * FP);
                a[mi][2] = *(const unsigned*)(p0 + 8);
                a[mi][3] = *(const unsigned*)(p0 + 8 * FP + 8);
            }
            unsigned b[4][2];
            #pragma unroll
            for (int nj = 0; nj < 4; nj++) {
                const __half* q0 = &Bs[cur][(wn + 8 * nj + gid) * FP + kh + 2 * tig];
                b[nj][0] = *(const unsigned*)(q0);
                b[nj][1] = *(const unsigned*)(q0 + 8);
            }
            #pragma unroll
            for (int mi = 0; mi < 4; mi++)
                #pragma unroll
                for (int nj = 0; nj < 4; nj++) {
                    asm volatile(
                        "mma.sync.aligned.m16n8k16.row.col.f32.f16.f16.f32 "
                        "{%0,%1,%2,%3}, {%4,%5,%6,%7}, {%8,%9}, {%0,%1,%2,%3};\n"
                        : "+f"(acc[mi][nj][0]), "+f"(acc[mi][nj][1]),
                          "+f"(acc[mi][nj][2]), "+f"(acc[mi][nj][3])
                        : "r"(a[mi][0]), "r"(a[mi][1]), "r"(a[mi][2]), "r"(a[mi][3]),
                          "r"(b[nj][0]), "r"(b[nj][1]));
                }
        }
        __syncthreads();
    }

    // epilogue
    #pragma unroll
    for (int mi = 0; mi < 4; mi++) {
        int row = bm + wm + 16 * mi + gid;
        #pragma unroll
        for (int nj = 0; nj < 4; nj++) {
            int col = bn + wn + 8 * nj + 2 * tig;
            float2 v0 = make_float2(acc[mi][nj][0], acc[mi][nj][1]);
            float2 v1 = make_float2(acc[mi][nj][2], acc[mi][nj][3]);
            float* c0 = &C[(size_t)row * N + col];
            float* c1 = &C[(size_t)(row + 8) * N + col];
            if (mode == 2) {
                float2 o0 = *(float2*)c0, o1 = *(float2*)c1;
                v0.x += o0.x; v0.y += o0.y;
                v1.x += o1.x; v1.y += o1.y;
            }
            *(float2*)c0 = v0;
            *(float2*)c1 = v1;
        }
    }
}

// ---------------- generic fp32 GEMM (dt projection): C = A*B^T ----------------
// mode 1: softplus(acc + bias[col])
__global__ __launch_bounds__(256) void gemm_nt(
    const float* __restrict__ A, const float* __restrict__ B,
    float* __restrict__ C, const float* __restrict__ bias,
    int M, int N, int K, int lda, int ldb, int ldc, int mode)
{
    __shared__ __align__(16) float As[16][68];
    __shared__ __align__(16) float Bs[16][68];
    const int bm = blockIdx.y * 64;
    const int bn = blockIdx.x * 64;
    const int tid = threadIdx.x;
    const int lrow = tid >> 2;
    const int lcol = (tid & 3) << 2;
    const int tr = (tid >> 4) << 2;
    const int tc = (tid & 15) << 2;

    float acc[4][4];
    #pragma unroll
    for (int i = 0; i < 4; i++)
        #pragma unroll
        for (int j = 0; j < 4; j++) acc[i][j] = 0.f;

    const bool bvalid = (bn + lrow) < N;
    const float* Aptr = A + (size_t)(bm + lrow) * lda + lcol;
    const float* Bptr = B + (size_t)(bn + lrow) * ldb + lcol;

    for (int k0 = 0; k0 < K; k0 += 16) {
        float4 av = *(const float4*)(Aptr + k0);
        float4 bv = make_float4(0.f, 0.f, 0.f, 0.f);
        if (bvalid) bv = *(const float4*)(Bptr + k0);
        As[lcol+0][lrow] = av.x; As[lcol+1][lrow] = av.y;
        As[lcol+2][lrow] = av.z; As[lcol+3][lrow] = av.w;
        Bs[lcol+0][lrow] = bv.x; Bs[lcol+1][lrow] = bv.y;
        Bs[lcol+2][lrow] = bv.z; Bs[lcol+3][lrow] = bv.w;
        __syncthreads();
        #pragma unroll
        for (int kk = 0; kk < 16; kk++) {
            float4 a = *(const float4*)&As[kk][tr];
            float4 b = *(const float4*)&Bs[kk][tc];
            acc[0][0] += a.x*b.x; acc[0][1] += a.x*b.y; acc[0][2] += a.x*b.z; acc[0][3] += a.x*b.w;
            acc[1][0] += a.y*b.x; acc[1][1] += a.y*b.y; acc[1][2] += a.y*b.z; acc[1][3] += a.y*b.w;
            acc[2][0] += a.z*b.x; acc[2][1] += a.z*b.y; acc[2][2] += a.z*b.z; acc[2][3] += a.z*b.w;
            acc[3][0] += a.w*b.x; acc[3][1] += a.w*b.y; acc[3][2] += a.w*b.z; acc[3][3] += a.w*b.w;
        }
        __syncthreads();
    }

    #pragma unroll
    for (int i = 0; i < 4; i++) {
        int row = bm + tr + i;
        #pragma unroll
        for (int j = 0; j < 4; j++) {
            int col = bn + tc + j;
            if (col < N) {
                float v = acc[i][j];
                if (mode == 1) {
                    v += bias[col];
                    v = (v > 20.f) ? v : log1pf(__expf(v));
                }
                C[(size_t)row * ldc + col] = v;
            }
        }
    }
}

// ---------------- depthwise causal conv (K=4) + SiLU; writes fp32 + fp16 ----------------
__global__ void conv_silu_kernel(const float* __restrict__ xz,
                                 const float* __restrict__ w,
                                 const float* __restrict__ b,
                                 float* __restrict__ xc,
                                 __half* __restrict__ xch)
{
    int idx = blockIdx.x * blockDim.x + threadIdx.x;
    if (idx >= BL * DINNER) return;
    int d  = idx % DINNER;
    int l  = (idx / DINNER) % LL;
    int bb = idx / (DINNER * LL);
    float s = b[d];
    #pragma unroll
    for (int k = 0; k < DCONV; k++) {
        int ll = l - (DCONV - 1) + k;
        if (ll >= 0)
            s += w[d * DCONV + k] * xz[(size_t)(bb * LL + ll) * (2 * DINNER) + d];
    }
    float v = s / (1.f + __expf(-s));   // silu
    xc[idx]  = v;
    xch[idx] = __float2half_rn(v);
}

// ---------------- selective scan (thread per (b,d) channel); fp16 y out ----------------
__global__ void scan_kernel(const float* __restrict__ xc,
                            const float* __restrict__ dt,
                            const float* __restrict__ xdbl,   // (BL, XDLD): [dt48|B16|C16|pad]
                            const float* __restrict__ xz,
                            const float* __restrict__ A_log,
                            const float* __restrict__ Dp,
                            __half* __restrict__ y)
{
    int c = blockIdx.x * blockDim.x + threadIdx.x;
    if (c >= BB * DINNER) return;
    int b = c / DINNER;
    int d = c - b * DINNER;

    float Av[DSTATE];
    #pragma unroll
    for (int n = 0; n < DSTATE; n++) Av[n] = -__expf(A_log[d * DSTATE + n]);
    const float Dv = Dp[d];

    float hs[DSTATE];
    #pragma unroll
    for (int n = 0; n < DSTATE; n++) hs[n] = 0.f;

    const float* dtp = dt + (size_t)b * LL * DINNER + d;
    const float* up  = xc + (size_t)b * LL * DINNER + d;
    const float* zp  = xz + (size_t)b * LL * (2 * DINNER) + DINNER + d;
    const float4* bc = (const float4*)xdbl + (size_t)b * LL * (XDLD/4) + 12;
    __half* yp = y + (size_t)b * LL * DINNER + d;

    for (int l = 0; l < LL; l++) {
        float dtv = dtp[(size_t)l * DINNER];
        float uv  = up [(size_t)l * DINNER];
        const float4* row = bc + (size_t)l * (XDLD/4);
        float4 b0 = row[0], b1 = row[1], b2 = row[2], b3 = row[3];
        float4 c0 = row[4], c1 = row[5], c2 = row[6], c3 = row[7];
        float Bv[16] = {b0.x,b0.y,b0.z,b0.w, b1.x,b1.y,b1.z,b1.w,
                        b2.x,b2.y,b2.z,b2.w, b3.x,b3.y,b3.z,b3.w};
        float Cv[16] = {c0.x,c0.y,c0.z,c0.w, c1.x,c1.y,c1.z,c1.w,
                        c2.x,c2.y,c2.z,c2.w, c3.x,c3.y,c3.z,c3.w};
        float du = dtv * uv;
        float accv = 0.f;
        #pragma unroll
        for (int n = 0; n < DSTATE; n++) {
            float dA = __expf(dtv * Av[n]);
            hs[n] = dA * hs[n] + du * Bv[n];
            accv += hs[n] * Cv[n];
        }
        float zv = zp[(size_t)l * (2 * DINNER)];
        float silz = zv / (1.f + __expf(-zv));
        yp[(size_t)l * DINNER] = __float2half_rn((accv + uv * Dv) * silz);
    }
}

// ---------------- layernorm (block per row), fp16 output ----------------
__global__ void layernorm_kernel(const float* __restrict__ x,
                                 const float* __restrict__ w,
                                 const float* __restrict__ b,
                                 __half* __restrict__ out)
{
    __shared__ float red[32];
    int row = blockIdx.x;
    const float* xr = x + (size_t)row * DMODEL;
    float s = 0.f, s2 = 0.f;
    for (int i = threadIdx.x; i < DMODEL; i += blockDim.x) {
        float v = xr[i];
        s += v; s2 += v * v;
    }
    #pragma unroll
    for (int o = 16; o > 0; o >>= 1) {
        s  += __shfl_down_sync(0xffffffff, s,  o);
        s2 += __shfl_down_sync(0xffffffff, s2, o);
    }
    int lane = threadIdx.x & 31, wid = threadIdx.x >> 5;
    if (lane == 0) { red[wid] = s; red[wid + 16] = s2; }
    __syncthreads();
    if (wid == 0) {
        int nw = blockDim.x >> 5;
        s  = (lane < nw) ? red[lane]      : 0.f;
        s2 = (lane < nw) ? red[lane + 16] : 0.f;
        #pragma unroll
        for (int o = 16; o > 0; o >>= 1) {
            s  += __shfl_down_sync(0xffffffff, s,  o);
            s2 += __shfl_down_sync(0xffffffff, s2, o);
        }
        if (lane == 0) { red[0] = s; red[1] = s2; }
    }
    __syncthreads();
    float mu  = red[0] / DMODEL;
    float var = red[1] / DMODEL - mu * mu;
    float rstd = rsqrtf(var + 1e-5f);
    for (int i = threadIdx.x; i < DMODEL; i += blockDim.x) {
        float v = (xr[i] - mu) * rstd * w[i] + b[i];
        out[(size_t)row * DMODEL + i] = __float2half_rn(v);
    }
}

// ---------------- host launcher ----------------
extern "C" void kernel_launch(void* const* d_in, const int* in_sizes, int n_in,
                              void* d_out, int out_size)
{
    const int*   x      = (const int*)  d_in[0];
    const float* emb    = (const float*)d_in[1];
    const float* in_w   = (const float*)d_in[2];
    const float* conv_w = (const float*)d_in[3];
    const float* conv_b = (const float*)d_in[4];
    const float* xp_w   = (const float*)d_in[5];
    const float* dt_w   = (const float*)d_in[6];
    const float* dt_b   = (const float*)d_in[7];
    const float* A_log  = (const float*)d_in[8];
    const float* Dp     = (const float*)d_in[9];
    const float* out_w  = (const float*)d_in[10];
    const float* ln_w   = (const float*)d_in[11];
    const float* ln_b   = (const float*)d_in[12];
    float* out = (float*)d_out;

    float *h, *xz, *xc, *xdbl, *dtb;
    __half *yh, *lnh, *hh, *xch, *embh, *inwh, *outwh, *xpwh;
    cudaGetSymbolAddress((void**)&h,     g_h);
    cudaGetSymbolAddress((void**)&xz,    g_xz);
    cudaGetSymbolAddress((void**)&xc,    g_xc);
    cudaGetSymbolAddress((void**)&xdbl,  g_xdbl);
    cudaGetSymbolAddress((void**)&dtb,   g_dt);
    cudaGetSymbolAddress((void**)&yh,    g_yh);
    cudaGetSymbolAddress((void**)&lnh,   g_lnh);
    cudaGetSymbolAddress((void**)&hh,    g_hh);
    cudaGetSymbolAddress((void**)&xch,   g_xch);
    cudaGetSymbolAddress((void**)&embh,  g_embh);
    cudaGetSymbolAddress((void**)&inwh,  g_inwh);
    cudaGetSymbolAddress((void**)&outwh, g_outwh);
    cudaGetSymbolAddress((void**)&xpwh,  g_xpwh);

    embed_kernel<<<(BL * DMODEL + 255) / 256, 256>>>(x, emb, h);

    // fp16 conversions (weights + embedding), once per launch
    cvt_f16_kernel<<<(VOCAB * DMODEL / 4 + 255) / 256, 256>>>(
        (const float4*)emb, (uint2*)embh, VOCAB * DMODEL / 4);
    cvt_f16_kernel<<<(NLAYERS * 2 * DINNER * DMODEL / 4 + 255) / 256, 256>>>(
        (const float4*)in_w, (uint2*)inwh, NLAYERS * 2 * DINNER * DMODEL / 4);
    cvt_f16_kernel<<<(NLAYERS * DMODEL * DINNER / 4 + 255) / 256, 256>>>(
        (const float4*)out_w, (uint2*)outwh, NLAYERS * DMODEL * DINNER / 4);
    xpw_pad_kernel<<<(NLAYERS * 128 * DINNER + 255) / 256, 256>>>(xp_w, xpwh);

    for (int i = 0; i < NLAYERS; i++) {
        // fp16 copy of residual stream for in_proj
        cvt_f16_kernel<<<(BL * DMODEL / 4 + 255) / 256, 256>>>(
            (const float4*)h, (uint2*)hh, BL * DMODEL / 4);

        // in_proj: xz(2048,3072) = h_f16 @ in_w_f16^T
        gemm_f16<<<dim3(BL / FTM, 2 * DINNER / FTN), 256>>>(
            hh, inwh + (size_t)i * 2 * DINNER * DMODEL, xz,
            BL, 2 * DINNER, DMODEL, 0);

        conv_silu_kernel<<<(BL * DINNER + 255) / 256, 256>>>(
            xz, conv_w + (size_t)i * DINNER * DCONV, conv_b + (size_t)i * DINNER,
            xc, xch);

        // x_proj: xdbl(2048,128pad) = xc_f16 @ xp_w_f16pad^T
        gemm_f16<<<dim3(BL / FTM, 1), 256>>>(
            xch, xpwh + (size_t)i * 128 * DINNER, xdbl,
            BL, 128, DINNER, 0);

        // dt: softplus(xdbl[:, :48] @ dt_w^T + dt_b)   (fp32 SIMT, K=48)
        gemm_nt<<<dim3(DINNER / 64, BL / 64), 256>>>(
            xdbl, dt_w + (size_t)i * DINNER * DTRANK, dtb, dt_b + (size_t)i * DINNER,
            BL, DINNER, DTRANK, XDLD, DTRANK, DINNER, 1);

        scan_kernel<<<(BB * DINNER + 255) / 256, 256>>>(
            xc, dtb, xdbl, xz, A_log + (size_t)i * DINNER * DSTATE,
            Dp + (size_t)i * DINNER, yh);

        // out_proj + residual: h += y_f16 @ out_w_f16^T
        gemm_f16<<<dim3(BL / FTM, DMODEL / FTN), 256>>>(
            yh, outwh + (size_t)i * DMODEL * DINNER, h,
            BL, DMODEL, DINNER, 2);
    }

    layernorm_kernel<<<BL, 256>>>(h, ln_w, ln_b, lnh);

    // lm_head: out(2048,32000) = ln_f16 @ emb_f16^T
    gemm_f16<<<dim3(BL / FTM, VOCAB / FTN), 256>>>(
        lnh, embh, out, BL, VOCAB, DMODEL, 0);
}

// round 8
// speedup vs baseline: 2.5483x; 1.0838x over previous
#include <cuda_runtime.h>
#include <cuda_fp16.h>
#include <cstdint>
#include <math.h>

// ---------------- model constants ----------------
#define VOCAB   32000
#define DMODEL  768
#define NLAYERS 2
#define DSTATE  16
#define DCONV   4
#define DINNER  1536
#define DTRANK  48
#define BB      2
#define LL      1024
#define BL      (BB*LL)          // 2048 rows
#define XDLD    128              // padded xdbl row stride

// ---------------- scratch (device globals; no cudaMalloc allowed) ----------------
__device__ float g_h   [BL * DMODEL];        // residual stream (fp32)
__device__ float g_xz  [BL * 2 * DINNER];
__device__ float g_xc  [BL * DINNER];        // conv+silu fp32 (scan input u)
__device__ float g_xdbl[BL * XDLD];          // x_proj out fp32 (scan reads B,C)
__device__ __half g_xdblh[BL * XDLD];        // x_proj out fp16 (dt GEMM input)
__device__ float g_dt  [BL * DINNER];
__device__ __half g_yh  [BL * DINNER];       // scan output (feeds out_proj)
__device__ __half g_lnh [BL * DMODEL];       // layernorm output (feeds lm_head)
__device__ __half g_hh  [BL * DMODEL];       // fp16 copy of h (feeds in_proj)
__device__ __half g_xch [BL * DINNER];       // fp16 copy of xc (feeds x_proj)
__device__ __half g_embh[VOCAB * DMODEL];
__device__ __half g_inwh[NLAYERS * 2 * DINNER * DMODEL];
__device__ __half g_outwh[NLAYERS * DMODEL * DINNER];
__device__ __half g_xpwh[NLAYERS * 128 * DINNER];   // xp_w padded 80->128 rows
__device__ __half g_dtwh[NLAYERS * DINNER * 64];    // dt_w padded K 48->64

// ---------------- embedding gather ----------------
__global__ void embed_kernel(const int* __restrict__ x,
                             const float* __restrict__ emb,
                             float* __restrict__ h) {
    int idx = blockIdx.x * blockDim.x + threadIdx.x;
    if (idx >= BL * DMODEL) return;
    int row = idx / DMODEL;
    int col = idx - row * DMODEL;
    h[idx] = emb[(size_t)x[row] * DMODEL + col];
}

// ---------------- fp32 -> fp16 convert ----------------
__global__ void cvt_f16_kernel(const float4* __restrict__ src,
                               uint2* __restrict__ dst, int n4) {
    int i = blockIdx.x * blockDim.x + threadIdx.x;
    if (i >= n4) return;
    float4 v = src[i];
    __half2 h01 = __float22half2_rn(make_float2(v.x, v.y));
    __half2 h23 = __float22half2_rn(make_float2(v.z, v.w));
    uint2 o;
    o.x = *(unsigned*)&h01;
    o.y = *(unsigned*)&h23;
    dst[i] = o;
}

// ---------------- xp_w pad: (80,1536) -> (128,1536) rows, zero pad ----------------
__global__ void xpw_pad_kernel(const float* __restrict__ src,
                               __half* __restrict__ dst) {
    int idx = blockIdx.x * blockDim.x + threadIdx.x;
    if (idx >= NLAYERS * 128 * DINNER) return;
    int layer = idx / (128 * DINNER);
    int rem   = idx - layer * 128 * DINNER;
    int row   = rem / DINNER;
    int col   = rem - row * DINNER;
    float v = 0.f;
    if (row < DTRANK + 2 * DSTATE)
        v = src[(size_t)layer * (DTRANK + 2 * DSTATE) * DINNER + row * DINNER + col];
    dst[idx] = __float2half_rn(v);
}

// ---------------- dt_w pad: (1536,48) -> (1536,64) cols, zero pad ----------------
__global__ void dtw_pad_kernel(const float* __restrict__ src,
                               __half* __restrict__ dst) {
    int idx = blockIdx.x * blockDim.x + threadIdx.x;
    if (idx >= NLAYERS * DINNER * 64) return;
    int layer = idx / (DINNER * 64);
    int rem   = idx - layer * DINNER * 64;
    int row   = rem / 64;
    int col   = rem - row * 64;
    float v = 0.f;
    if (col < DTRANK)
        v = src[(size_t)layer * DINNER * DTRANK + row * DTRANK + col];
    dst[idx] = __float2half_rn(v);
}

// ---------------- fp16 tensor-core GEMM: C(MxN) = A(MxK_lda) * B(NxK_ldb)^T ----------------
// mode 0: store f32; mode 1: softplus(acc + bias[col]) f32; mode 2: C += acc;
// mode 4: store f32 C and f16 Ch.
// 256 threads, 128x128x32 tile, warp tile 64x32, mma.m16n8k16, ldmatrix frags, 2 CTA/SM.
#define FTM 128
#define FTN 128
#define FTK 32      // halves per K tile
#define FP  40      // smem pitch (halves); ldmatrix conflict-free
#define FBUF (128 * FP)
#define FBUF_B (FBUF * 2)

__device__ __forceinline__ void cp_async16(unsigned saddr, const void* gaddr) {
    asm volatile("cp.async.ca.shared.global [%0], [%1], 16;\n"
                 :: "r"(saddr), "l"(gaddr));
}
__device__ __forceinline__ void ldmx4(unsigned& r0, unsigned& r1,
                                      unsigned& r2, unsigned& r3, unsigned addr) {
    asm volatile("ldmatrix.sync.aligned.m8n8.x4.shared.b16 {%0,%1,%2,%3}, [%4];"
                 : "=r"(r0), "=r"(r1), "=r"(r2), "=r"(r3) : "r"(addr));
}

__global__ __launch_bounds__(256, 2) void gemm_f16(
    const __half* __restrict__ A, const __half* __restrict__ B,
    float* __restrict__ C, __half* __restrict__ Ch,
    const float* __restrict__ bias,
    int M, int N, int K, int lda, int ldb, int mode)
{
    __shared__ __align__(16) __half As[2][FBUF];
    __shared__ __align__(16) __half Bs[2][FBUF];

    const int bm = blockIdx.x * FTM;
    const int bn = blockIdx.y * FTN;
    const int tid  = threadIdx.x;
    const int warp = tid >> 5;
    const int lane = tid & 31;
    const int wm = (warp & 1) * 64;
    const int wn = (warp >> 1) * 32;
    const int gid = lane >> 2;
    const int tig = lane & 3;

    // loader mapping: thread loads 16B at (row, 16B-col)
    const int lrow = tid >> 2;        // 0..63
    const int lcb  = (tid & 3) * 16;  // byte col within 64B (=FTK halves)

    // ldmatrix per-lane smem offsets (bytes, buffer 0, ks 0)
    unsigned aoff[4], boff[2];
    {
        int arow = lane & 15;
        int acol = (lane >> 4) << 3;          // 0 or 8 halves
        #pragma unroll
        for (int mi = 0; mi < 4; mi++)
            aoff[mi] = (unsigned)(((wm + 16 * mi + arow) * FP + acol) * 2);
        int brow = lane & 7;
        int bsel = (lane >> 4) & 1;
        int bcol = ((lane >> 3) & 1) << 3;
        #pragma unroll
        for (int njp = 0; njp < 2; njp++)
            boff[njp] = (unsigned)(((wn + 8 * (2 * njp + bsel) + brow) * FP + bcol) * 2);
    }

    float acc[4][4][4];
    #pragma unroll
    for (int i = 0; i < 4; i++)
        #pragma unroll
        for (int j = 0; j < 4; j++)
            #pragma unroll
            for (int r = 0; r < 4; r++) acc[i][j][r] = 0.f;

    unsigned sA = (unsigned)__cvta_generic_to_shared(&As[0][0]);
    unsigned sB = (unsigned)__cvta_generic_to_shared(&Bs[0][0]);
    const int KT = K / FTK;

    // prologue: tile 0
    {
        #pragma unroll
        for (int p = 0; p < 2; p++) {
            int row = lrow + 64 * p;
            unsigned soff = (unsigned)(row * FP * 2 + lcb);
            cp_async16(sA + soff, (const char*)(A + (size_t)(bm + row) * lda) + lcb);
            cp_async16(sB + soff, (const char*)(B + (size_t)(bn + row) * ldb) + lcb);
        }
        asm volatile("cp.async.commit_group;\n");
    }

    for (int kt = 0; kt < KT; kt++) {
        int cur = kt & 1;
        if (kt + 1 < KT) {
            int nxt = (kt + 1) & 1;
            size_t kbyte = (size_t)(kt + 1) * FTK * 2;
            #pragma unroll
            for (int p = 0; p < 2; p++) {
                int row = lrow + 64 * p;
                unsigned soff = (unsigned)(nxt * FBUF_B + row * FP * 2 + lcb);
                cp_async16(sA + soff,
                           (const char*)(A + (size_t)(bm + row) * lda) + kbyte + lcb);
                cp_async16(sB + soff,
                           (const char*)(B + (size_t)(bn + row) * ldb) + kbyte + lcb);
            }
            asm volatile("cp.async.commit_group;\n");
            asm volatile("cp.async.wait_group 1;\n");
        } else {
            asm volatile("cp.async.wait_group 0;\n");
        }
        __syncthreads();

        unsigned abase = sA + cur * FBUF_B;
        unsigned bbase = sB + cur * FBUF_B;
        #pragma unroll
        for (int ks = 0; ks < 2; ks++) {
            unsigned kadd = ks * 32;   // 16 halves
            unsigned a[4][4];
            #pragma unroll
            for (int mi = 0; mi < 4; mi++)
                ldmx4(a[mi][0], a[mi][1], a[mi][2], a[mi][3], abase + aoff[mi] + kadd);
            unsigned bf[4][2];
            #pragma unroll
            for (int njp = 0; njp < 2; njp++)
                ldmx4(bf[2*njp][0], bf[2*njp][1], bf[2*njp+1][0], bf[2*njp+1][1],
                      bbase + boff[njp] + kadd);
            #pragma unroll
            for (int mi = 0; mi < 4; mi++)
                #pragma unroll
                for (int nj = 0; nj < 4; nj++) {
                    asm volatile(
                        "mma.sync.aligned.m16n8k16.row.col.f32.f16.f16.f32 "
                        "{%0,%1,%2,%3}, {%4,%5,%6,%7}, {%8,%9}, {%0,%1,%2,%3};\n"
                        : "+f"(acc[mi][nj][0]), "+f"(acc[mi][nj][1]),
                          "+f"(acc[mi][nj][2]), "+f"(acc[mi][nj][3])
                        : "r"(a[mi][0]), "r"(a[mi][1]), "r"(a[mi][2]), "r"(a[mi][3]),
                          "r"(bf[nj][0]), "r"(bf[nj][1]));
                }
        }
        __syncthreads();
    }

    // epilogue
    #pragma unroll
    for (int mi = 0; mi < 4; mi++) {
        int row = bm + wm + 16 * mi + gid;
        #pragma unroll
        for (int nj = 0; nj < 4; nj++) {
            int col = bn + wn + 8 * nj + 2 * tig;
            float v[4] = {acc[mi][nj][0], acc[mi][nj][1],
                          acc[mi][nj][2], acc[mi][nj][3]};
            if (mode == 1) {
                float b0 = bias[col], b1 = bias[col + 1];
                v[0] += b0; v[1] += b1; v[2] += b0; v[3] += b1;
                #pragma unroll
                for (int r = 0; r < 4; r++)
                    v[r] = (v[r] > 20.f) ? v[r] : log1pf(__expf(v[r]));
            }
            float* c0 = &C[(size_t)row * N + col];
            float* c1 = &C[(size_t)(row + 8) * N + col];
            if (mode == 2) {
                float2 o0 = *(float2*)c0, o1 = *(float2*)c1;
                v[0] += o0.x; v[1] += o0.y;
                v[2] += o1.x; v[3] += o1.y;
            }
            *(float2*)c0 = make_float2(v[0], v[1]);
            *(float2*)c1 = make_float2(v[2], v[3]);
            if (mode == 4) {
                __half2 h0 = __float22half2_rn(make_float2(v[0], v[1]));
                __half2 h1 = __float22half2_rn(make_float2(v[2], v[3]));
                *(__half2*)&Ch[(size_t)row * N + col]       = h0;
                *(__half2*)&Ch[(size_t)(row + 8) * N + col] = h1;
            }
        }
    }
}

// ---------------- depthwise causal conv (K=4) + SiLU; fp32 + fp16 out ----------------
__global__ void conv_silu_kernel(const float* __restrict__ xz,
                                 const float* __restrict__ w,
                                 const float* __restrict__ b,
                                 float* __restrict__ xc,
                                 __half* __restrict__ xch)
{
    int idx = blockIdx.x * blockDim.x + threadIdx.x;
    if (idx >= BL * DINNER) return;
    int d  = idx % DINNER;
    int l  = (idx / DINNER) % LL;
    int bb = idx / (DINNER * LL);
    float s = b[d];
    #pragma unroll
    for (int k = 0; k < DCONV; k++) {
        int ll = l - (DCONV - 1) + k;
        if (ll >= 0)
            s += w[d * DCONV + k] * xz[(size_t)(bb * LL + ll) * (2 * DINNER) + d];
    }
    float v = s / (1.f + __expf(-s));
    xc[idx]  = v;
    xch[idx] = __float2half_rn(v);
}

// ---------------- selective scan: lane = (channel, state), 16 lanes/channel ----------------
__global__ void scan_kernel(const float* __restrict__ xc,
                            const float* __restrict__ dt,
                            const float* __restrict__ xdbl,
                            const float* __restrict__ xz,
                            const float* __restrict__ A_log,
                            const float* __restrict__ Dp,
                            __half* __restrict__ y)
{
    int gw   = (blockIdx.x * blockDim.x + threadIdx.x) >> 5;  // global warp id
    int lane = threadIdx.x & 31;
    int half = lane >> 4;       // channel within warp
    int n    = lane & 15;       // state index
    int c = gw * 2 + half;
    if (c >= BB * DINNER) return;
    int b = c / DINNER;
    int d = c - b * DINNER;

    float Av = -__expf(A_log[d * DSTATE + n]);
    float Dv = Dp[d];
    float hs = 0.f;

    const float* dtp = dt + (size_t)b * LL * DINNER + d;
    const float* up  = xc + (size_t)b * LL * DINNER + d;
    const float* zp  = xz + (size_t)b * LL * (2 * DINNER) + DINNER + d;
    const float* bcp = xdbl + (size_t)b * LL * XDLD + 48 + n;   // B@+48, C@+64
    __half* yp = y + (size_t)b * LL * DINNER + d;

    for (int l = 0; l < LL; l++) {
        float dtv = dtp[(size_t)l * DINNER];
        float uv  = up [(size_t)l * DINNER];
        float Bv  = bcp[(size_t)l * XDLD];
        float Cv  = bcp[(size_t)l * XDLD + 16];
        float dA  = __expf(dtv * Av);
        hs = dA * hs + (dtv * uv) * Bv;
        float p = hs * Cv;
        #pragma unroll
        for (int o = 8; o > 0; o >>= 1)
            p += __shfl_xor_sync(0xffffffffu, p, o);
        if (n == 0) {
            float zv = zp[(size_t)l * (2 * DINNER)];
            float silz = zv / (1.f + __expf(-zv));
            yp[(size_t)l * DINNER] = __float2half_rn((p + uv * Dv) * silz);
        }
    }
}

// ---------------- layernorm (block per row), fp16 output ----------------
__global__ void layernorm_kernel(const float* __restrict__ x,
                                 const float* __restrict__ w,
                                 const float* __restrict__ b,
                                 __half* __restrict__ out)
{
    __shared__ float red[32];
    int row = blockIdx.x;
    const float* xr = x + (size_t)row * DMODEL;
    float s = 0.f, s2 = 0.f;
    for (int i = threadIdx.x; i < DMODEL; i += blockDim.x) {
        float v = xr[i];
        s += v; s2 += v * v;
    }
    #pragma unroll
    for (int o = 16; o > 0; o >>= 1) {
        s  += __shfl_down_sync(0xffffffff, s,  o);
        s2 += __shfl_down_sync(0xffffffff, s2, o);
    }
    int lane = threadIdx.x & 31, wid = threadIdx.x >> 5;
    if (lane == 0) { red[wid] = s; red[wid + 16] = s2; }
    __syncthreads();
    if (wid == 0) {
        int nw = blockDim.x >> 5;
        s  = (lane < nw) ? red[lane]      : 0.f;
        s2 = (lane < nw) ? red[lane + 16] : 0.f;
        #pragma unroll
        for (int o = 16; o > 0; o >>= 1) {
            s  += __shfl_down_sync(0xffffffff, s,  o);
            s2 += __shfl_down_sync(0xffffffff, s2, o);
        }
        if (lane == 0) { red[0] = s; red[1] = s2; }
    }
    __syncthreads();
    float mu  = red[0] / DMODEL;
    float var = red[1] / DMODEL - mu * mu;
    float rstd = rsqrtf(var + 1e-5f);
    for (int i = threadIdx.x; i < DMODEL; i += blockDim.x) {
        float v = (xr[i] - mu) * rstd * w[i] + b[i];
        out[(size_t)row * DMODEL + i] = __float2half_rn(v);
    }
}

// ---------------- host launcher ----------------
extern "C" void kernel_launch(void* const* d_in, const int* in_sizes, int n_in,
                              void* d_out, int out_size)
{
    const int*   x      = (const int*)  d_in[0];
    const float* emb    = (const float*)d_in[1];
    const float* in_w   = (const float*)d_in[2];
    const float* conv_w = (const float*)d_in[3];
    const float* conv_b = (const float*)d_in[4];
    const float* xp_w   = (const float*)d_in[5];
    const float* dt_w   = (const float*)d_in[6];
    const float* dt_b   = (const float*)d_in[7];
    const float* A_log  = (const float*)d_in[8];
    const float* Dp     = (const float*)d_in[9];
    const float* out_w  = (const float*)d_in[10];
    const float* ln_w   = (const float*)d_in[11];
    const float* ln_b   = (const float*)d_in[12];
    float* out = (float*)d_out;

    float *h, *xz, *xc, *xdbl, *dtb;
    __half *xdblh, *yh, *lnh, *hh, *xch, *embh, *inwh, *outwh, *xpwh, *dtwh;
    cudaGetSymbolAddress((void**)&h,     g_h);
    cudaGetSymbolAddress((void**)&xz,    g_xz);
    cudaGetSymbolAddress((void**)&xc,    g_xc);
    cudaGetSymbolAddress((void**)&xdbl,  g_xdbl);
    cudaGetSymbolAddress((void**)&xdblh, g_xdblh);
    cudaGetSymbolAddress((void**)&dtb,   g_dt);
    cudaGetSymbolAddress((void**)&yh,    g_yh);
    cudaGetSymbolAddress((void**)&lnh,   g_lnh);
    cudaGetSymbolAddress((void**)&hh,    g_hh);
    cudaGetSymbolAddress((void**)&xch,   g_xch);
    cudaGetSymbolAddress((void**)&embh,  g_embh);
    cudaGetSymbolAddress((void**)&inwh,  g_inwh);
    cudaGetSymbolAddress((void**)&outwh, g_outwh);
    cudaGetSymbolAddress((void**)&xpwh,  g_xpwh);
    cudaGetSymbolAddress((void**)&dtwh,  g_dtwh);

    // launches 1-5 (so launch #6 = in_proj gemm_f16 lands under ncu -s 5 -c 1)
    embed_kernel<<<(BL * DMODEL + 255) / 256, 256>>>(x, emb, h);                 // 1
    cvt_f16_kernel<<<(VOCAB * DMODEL / 4 + 255) / 256, 256>>>(
        (const float4*)emb, (uint2*)embh, VOCAB * DMODEL / 4);                   // 2
    cvt_f16_kernel<<<(NLAYERS * 2 * DINNER * DMODEL / 4 + 255) / 256, 256>>>(
        (const float4*)in_w, (uint2*)inwh, NLAYERS * 2 * DINNER * DMODEL / 4);   // 3
    cvt_f16_kernel<<<(NLAYERS * DMODEL * DINNER / 4 + 255) / 256, 256>>>(
        (const float4*)out_w, (uint2*)outwh, NLAYERS * DMODEL * DINNER / 4);     // 4

    for (int i = 0; i < NLAYERS; i++) {
        cvt_f16_kernel<<<(BL * DMODEL / 4 + 255) / 256, 256>>>(
            (const float4*)h, (uint2*)hh, BL * DMODEL / 4);                      // 5 (i=0)

        // in_proj: xz(2048,3072) = h_f16 @ in_w_f16^T                           // 6 (i=0)
        gemm_f16<<<dim3(BL / FTM, 2 * DINNER / FTN), 256>>>(
            hh, inwh + (size_t)i * 2 * DINNER * DMODEL, xz, nullptr, nullptr,
            BL, 2 * DINNER, DMODEL, DMODEL, DMODEL, 0);

        if (i == 0) {
            xpw_pad_kernel<<<(NLAYERS * 128 * DINNER + 255) / 256, 256>>>(xp_w, xpwh);
            dtw_pad_kernel<<<(NLAYERS * DINNER * 64 + 255) / 256, 256>>>(dt_w, dtwh);
        }

        conv_silu_kernel<<<(BL * DINNER + 255) / 256, 256>>>(
            xz, conv_w + (size_t)i * DINNER * DCONV, conv_b + (size_t)i * DINNER,
            xc, xch);

        // x_proj: xdbl(2048,128) fp32+fp16 = xc_f16 @ xp_w_pad^T
        gemm_f16<<<dim3(BL / FTM, 1), 256>>>(
            xch, xpwh + (size_t)i * 128 * DINNER, xdbl, xdblh, nullptr,
            BL, 128, DINNER, DINNER, DINNER, 4);

        // dt: softplus(xdblh[:, :64] @ dtwh^T + dt_b), K=64 (cols 48-63 x 0-pad = 0)
        gemm_f16<<<dim3(BL / FTM, DINNER / FTN), 256>>>(
            xdblh, dtwh + (size_t)i * DINNER * 64, dtb, nullptr,
            dt_b + (size_t)i * DINNER,
            BL, DINNER, 64, XDLD, 64, 1);

        scan_kernel<<<(BB * DINNER * 16 + 255) / 256, 256>>>(
            xc, dtb, xdbl, xz, A_log + (size_t)i * DINNER * DSTATE,
            Dp + (size_t)i * DINNER, yh);

        // out_proj + residual: h += y_f16 @ out_w_f16^T
        gemm_f16<<<dim3(BL / FTM, DMODEL / FTN), 256>>>(
            yh, outwh + (size_t)i * DMODEL * DINNER, h, nullptr, nullptr,
            BL, DMODEL, DINNER, DINNER, DINNER, 2);
    }

    layernorm_kernel<<<BL, 256>>>(h, ln_w, ln_b, lnh);

    // lm_head: out(2048,32000) = ln_f16 @ emb_f16^T
    gemm_f16<<<dim3(BL / FTM, VOCAB / FTN), 256>>>(
        lnh, embh, out, nullptr, nullptr, BL, VOCAB, DMODEL, DMODEL, DMODEL, 0);
}

// round 9
// speedup vs baseline: 2.5710x; 1.0089x over previous
#include <cuda_runtime.h>
#include <cuda_fp16.h>
#include <cstdint>
#include <math.h>

// ---------------- model constants ----------------
#define VOCAB   32000
#define DMODEL  768
#define NLAYERS 2
#define DSTATE  16
#define DCONV   4
#define DINNER  1536
#define DTRANK  48
#define BB      2
#define LL      1024
#define BL      (BB*LL)          // 2048 rows
#define XDLD    128              // padded xdbl row stride

// ---------------- scratch (device globals; no cudaMalloc allowed) ----------------
__device__ float g_h   [BL * DMODEL];        // residual stream (fp32)
__device__ float g_xz  [BL * 2 * DINNER];
__device__ float g_xc  [BL * DINNER];        // conv+silu fp32 (scan input u)
__device__ float g_xdbl[BL * XDLD];          // x_proj out fp32 (scan reads B,C)
__device__ __half g_xdblh[BL * XDLD];        // x_proj out fp16 (dt GEMM input)
__device__ float g_dt  [BL * DINNER];
__device__ __half g_yh  [BL * DINNER];       // scan output (feeds out_proj)
__device__ __half g_lnh [BL * DMODEL];       // layernorm output (feeds lm_head)
__device__ __half g_hh  [BL * DMODEL];       // fp16 mirror of h (feeds in_proj)
__device__ __half g_xch [BL * DINNER];       // fp16 copy of xc (feeds x_proj)
__device__ __half g_embh[VOCAB * DMODEL];
__device__ __half g_inwh[NLAYERS * 2 * DINNER * DMODEL];
__device__ __half g_outwh[NLAYERS * DMODEL * DINNER];
__device__ __half g_xpwh[NLAYERS * 128 * DINNER];   // xp_w padded 80->128 rows
__device__ __half g_dtwh[NLAYERS * DINNER * 64];    // dt_w padded K 48->64

// ---------------- embedding gather (fp32 + fp16 mirror) ----------------
__global__ void embed_kernel(const int* __restrict__ x,
                             const float* __restrict__ emb,
                             float* __restrict__ h,
                             __half* __restrict__ hh) {
    int idx = blockIdx.x * blockDim.x + threadIdx.x;
    if (idx >= BL * DMODEL) return;
    int row = idx / DMODEL;
    int col = idx - row * DMODEL;
    float v = emb[(size_t)x[row] * DMODEL + col];
    h[idx]  = v;
    hh[idx] = __float2half_rn(v);
}

// ---------------- fp32 -> fp16 convert ----------------
__global__ void cvt_f16_kernel(const float4* __restrict__ src,
                               uint2* __restrict__ dst, int n4) {
    int i = blockIdx.x * blockDim.x + threadIdx.x;
    if (i >= n4) return;
    float4 v = src[i];
    __half2 h01 = __float22half2_rn(make_float2(v.x, v.y));
    __half2 h23 = __float22half2_rn(make_float2(v.z, v.w));
    uint2 o;
    o.x = *(unsigned*)&h01;
    o.y = *(unsigned*)&h23;
    dst[i] = o;
}

// ---------------- xp_w pad: (80,1536) -> (128,1536) rows, zero pad ----------------
__global__ void xpw_pad_kernel(const float* __restrict__ src,
                               __half* __restrict__ dst) {
    int idx = blockIdx.x * blockDim.x + threadIdx.x;
    if (idx >= NLAYERS * 128 * DINNER) return;
    int layer = idx / (128 * DINNER);
    int rem   = idx - layer * 128 * DINNER;
    int row   = rem / DINNER;
    int col   = rem - row * DINNER;
    float v = 0.f;
    if (row < DTRANK + 2 * DSTATE)
        v = src[(size_t)layer * (DTRANK + 2 * DSTATE) * DINNER + row * DINNER + col];
    dst[idx] = __float2half_rn(v);
}

// ---------------- dt_w pad: (1536,48) -> (1536,64) cols, zero pad ----------------
__global__ void dtw_pad_kernel(const float* __restrict__ src,
                               __half* __restrict__ dst) {
    int idx = blockIdx.x * blockDim.x + threadIdx.x;
    if (idx >= NLAYERS * DINNER * 64) return;
    int layer = idx / (DINNER * 64);
    int rem   = idx - layer * DINNER * 64;
    int row   = rem / 64;
    int col   = rem - row * 64;
    float v = 0.f;
    if (col < DTRANK)
        v = src[(size_t)layer * DINNER * DTRANK + row * DTRANK + col];
    dst[idx] = __float2half_rn(v);
}

// ---------------- fp16 tensor-core GEMM: C(MxN) = A(MxK_lda) * B(NxK_ldb)^T ----------------
// mode bits: 1 = softplus(acc+bias); 2 = residual add into C; 4 = also write f16 Ch.
// 256 threads, 128x128x32 tile, warp tile 64x32, mma.m16n8k16, ldmatrix, 3-stage pipeline.
#define FTM 128
#define FTN 128
#define FTK 32      // halves per K tile
#define FP  40      // smem pitch (halves)
#define FBUF (128 * FP)           // halves per stage per operand
#define FBUF_B (FBUF * 2)         // bytes
#define NSTAGE 3
#define GEMM_SMEM (NSTAGE * FBUF_B * 2)   // 61440 bytes

__device__ __forceinline__ void cp_async16(unsigned saddr, const void* gaddr) {
    asm volatile("cp.async.ca.shared.global [%0], [%1], 16;\n"
                 :: "r"(saddr), "l"(gaddr));
}
__device__ __forceinline__ void ldmx4(unsigned& r0, unsigned& r1,
                                      unsigned& r2, unsigned& r3, unsigned addr) {
    asm volatile("ldmatrix.sync.aligned.m8n8.x4.shared.b16 {%0,%1,%2,%3}, [%4];"
                 : "=r"(r0), "=r"(r1), "=r"(r2), "=r"(r3) : "r"(addr));
}

__global__ __launch_bounds__(256, 2) void gemm_f16(
    const __half* __restrict__ A, const __half* __restrict__ B,
    float* __restrict__ C, __half* __restrict__ Ch,
    const float* __restrict__ bias,
    int M, int N, int K, int lda, int ldb, int mode)
{
    extern __shared__ __half smemh[];
    unsigned sA = (unsigned)__cvta_generic_to_shared(smemh);
    unsigned sB = sA + NSTAGE * FBUF_B;

    const int bm = blockIdx.x * FTM;
    const int bn = blockIdx.y * FTN;
    const int tid  = threadIdx.x;
    const int warp = tid >> 5;
    const int lane = tid & 31;
    const int wm = (warp & 1) * 64;
    const int wn = (warp >> 1) * 32;
    const int gid = lane >> 2;
    const int tig = lane & 3;

    const int lrow = tid >> 2;        // 0..63
    const int lcb  = (tid & 3) * 16;  // byte col within 64B

    // ldmatrix per-lane offsets (bytes, stage 0)
    unsigned aoff[4], boff[2];
    {
        int arow = lane & 15;
        int acol = (lane >> 4) << 3;
        #pragma unroll
        for (int mi = 0; mi < 4; mi++)
            aoff[mi] = (unsigned)(((wm + 16 * mi + arow) * FP + acol) * 2);
        int brow = lane & 7;
        int bsel = (lane >> 4) & 1;
        int bcol = ((lane >> 3) & 1) << 3;
        #pragma unroll
        for (int njp = 0; njp < 2; njp++)
            boff[njp] = (unsigned)(((wn + 8 * (2 * njp + bsel) + brow) * FP + bcol) * 2);
    }

    float acc[4][4][4];
    #pragma unroll
    for (int i = 0; i < 4; i++)
        #pragma unroll
        for (int j = 0; j < 4; j++)
            #pragma unroll
            for (int r = 0; r < 4; r++) acc[i][j][r] = 0.f;

    const int KT = K / FTK;

    // prologue: load tiles 0,1 into stages 0,1
    #pragma unroll
    for (int s = 0; s < 2; s++) {
        if (s < KT) {
            size_t kbyte = (size_t)s * FTK * 2;
            #pragma unroll
            for (int p = 0; p < 2; p++) {
                int row = lrow + 64 * p;
                unsigned soff = (unsigned)(s * FBUF_B + row * FP * 2 + lcb);
                cp_async16(sA + soff,
                           (const char*)(A + (size_t)(bm + row) * lda) + kbyte + lcb);
                cp_async16(sB + soff,
                           (const char*)(B + (size_t)(bn + row) * ldb) + kbyte + lcb);
            }
        }
        asm volatile("cp.async.commit_group;\n");
    }

    for (int kt = 0; kt < KT; kt++) {
        // issue load for tile kt+2 into stage (kt+2)%3
        int ld = kt + 2;
        if (ld < KT) {
            int st = ld % NSTAGE;
            size_t kbyte = (size_t)ld * FTK * 2;
            #pragma unroll
            for (int p = 0; p < 2; p++) {
                int row = lrow + 64 * p;
                unsigned soff = (unsigned)(st * FBUF_B + row * FP * 2 + lcb);
                cp_async16(sA + soff,
                           (const char*)(A + (size_t)(bm + row) * lda) + kbyte + lcb);
                cp_async16(sB + soff,
                           (const char*)(B + (size_t)(bn + row) * ldb) + kbyte + lcb);
            }
        }
        asm volatile("cp.async.commit_group;\n");
        asm volatile("cp.async.wait_group %0;\n" :: "n"(NSTAGE - 1));
        __syncthreads();

        int cur = kt % NSTAGE;
        unsigned abase = sA + cur * FBUF_B;
        unsigned bbase = sB + cur * FBUF_B;
        #pragma unroll
        for (int ks = 0; ks < 2; ks++) {
            unsigned kadd = ks * 32;
            unsigned a[4][4];
            #pragma unroll
            for (int mi = 0; mi < 4; mi++)
                ldmx4(a[mi][0], a[mi][1], a[mi][2], a[mi][3], abase + aoff[mi] + kadd);
            unsigned bf[4][2];
            #pragma unroll
            for (int njp = 0; njp < 2; njp++)
                ldmx4(bf[2*njp][0], bf[2*njp][1], bf[2*njp+1][0], bf[2*njp+1][1],
                      bbase + boff[njp] + kadd);
            #pragma unroll
            for (int mi = 0; mi < 4; mi++)
                #pragma unroll
                for (int nj = 0; nj < 4; nj++) {
                    asm volatile(
                        "mma.sync.aligned.m16n8k16.row.col.f32.f16.f16.f32 "
                        "{%0,%1,%2,%3}, {%4,%5,%6,%7}, {%8,%9}, {%0,%1,%2,%3};\n"
                        : "+f"(acc[mi][nj][0]), "+f"(acc[mi][nj][1]),
                          "+f"(acc[mi][nj][2]), "+f"(acc[mi][nj][3])
                        : "r"(a[mi][0]), "r"(a[mi][1]), "r"(a[mi][2]), "r"(a[mi][3]),
                          "r"(bf[nj][0]), "r"(bf[nj][1]));
                }
        }
        __syncthreads();
    }

    // epilogue
    #pragma unroll
    for (int mi = 0; mi < 4; mi++) {
        int row = bm + wm + 16 * mi + gid;
        #pragma unroll
        for (int nj = 0; nj < 4; nj++) {
            int col = bn + wn + 8 * nj + 2 * tig;
            float v[4] = {acc[mi][nj][0], acc[mi][nj][1],
                          acc[mi][nj][2], acc[mi][nj][3]};
            if (mode & 1) {
                float b0 = bias[col], b1 = bias[col + 1];
                v[0] += b0; v[1] += b1; v[2] += b0; v[3] += b1;
                #pragma unroll
                for (int r = 0; r < 4; r++)
                    v[r] = (v[r] > 20.f) ? v[r] : log1pf(__expf(v[r]));
            }
            float* c0 = &C[(size_t)row * N + col];
            float* c1 = &C[(size_t)(row + 8) * N + col];
            if (mode & 2) {
                float2 o0 = *(float2*)c0, o1 = *(float2*)c1;
                v[0] += o0.x; v[1] += o0.y;
                v[2] += o1.x; v[3] += o1.y;
            }
            *(float2*)c0 = make_float2(v[0], v[1]);
            *(float2*)c1 = make_float2(v[2], v[3]);
            if (mode & 4) {
                __half2 h0 = __float22half2_rn(make_float2(v[0], v[1]));
                __half2 h1 = __float22half2_rn(make_float2(v[2], v[3]));
                *(__half2*)&Ch[(size_t)row * N + col]       = h0;
                *(__half2*)&Ch[(size_t)(row + 8) * N + col] = h1;
            }
        }
    }
}

// ---------------- depthwise causal conv (K=4) + SiLU; fp32 + fp16 out ----------------
__global__ void conv_silu_kernel(const float* __restrict__ xz,
                                 const float* __restrict__ w,
                                 const float* __restrict__ b,
                                 float* __restrict__ xc,
                                 __half* __restrict__ xch)
{
    int idx = blockIdx.x * blockDim.x + threadIdx.x;
    if (idx >= BL * DINNER) return;
    int d  = idx % DINNER;
    int l  = (idx / DINNER) % LL;
    int bb = idx / (DINNER * LL);
    float s = b[d];
    #pragma unroll
    for (int k = 0; k < DCONV; k++) {
        int ll = l - (DCONV - 1) + k;
        if (ll >= 0)
            s += w[d * DCONV + k] * xz[(size_t)(bb * LL + ll) * (2 * DINNER) + d];
    }
    float v = s / (1.f + __expf(-s));
    xc[idx]  = v;
    xch[idx] = __float2half_rn(v);
}

// ---------------- selective scan: lane = (channel, state), 16 lanes/channel ----------------
__global__ void scan_kernel(const float* __restrict__ xc,
                            const float* __restrict__ dt,
                            const float* __restrict__ xdbl,
                            const float* __restrict__ xz,
                            const float* __restrict__ A_log,
                            const float* __restrict__ Dp,
                            __half* __restrict__ y)
{
    int gw   = (blockIdx.x * blockDim.x + threadIdx.x) >> 5;
    int lane = threadIdx.x & 31;
    int half = lane >> 4;
    int n    = lane & 15;
    int c = gw * 2 + half;
    if (c >= BB * DINNER) return;
    int b = c / DINNER;
    int d = c - b * DINNER;

    float Av = -__expf(A_log[d * DSTATE + n]);
    float Dv = Dp[d];
    float hs = 0.f;

    const float* dtp = dt + (size_t)b * LL * DINNER + d;
    const float* up  = xc + (size_t)b * LL * DINNER + d;
    const float* zp  = xz + (size_t)b * LL * (2 * DINNER) + DINNER + d;
    const float* bcp = xdbl + (size_t)b * LL * XDLD + 48 + n;
    __half* yp = y + (size_t)b * LL * DINNER + d;

    for (int l = 0; l < LL; l++) {
        float dtv = dtp[(size_t)l * DINNER];
        float uv  = up [(size_t)l * DINNER];
        float Bv  = bcp[(size_t)l * XDLD];
        float Cv  = bcp[(size_t)l * XDLD + 16];
        float dA  = __expf(dtv * Av);
        hs = dA * hs + (dtv * uv) * Bv;
        float p = hs * Cv;
        #pragma unroll
        for (int o = 8; o > 0; o >>= 1)
            p += __shfl_xor_sync(0xffffffffu, p, o);
        if (n == 0) {
            float zv = zp[(size_t)l * (2 * DINNER)];
            float silz = zv / (1.f + __expf(-zv));
            yp[(size_t)l * DINNER] = __float2half_rn((p + uv * Dv) * silz);
        }
    }
}

// ---------------- layernorm (block per row), fp16 output ----------------
__global__ void layernorm_kernel(const float* __restrict__ x,
                                 const float* __restrict__ w,
                                 const float* __restrict__ b,
                                 __half* __restrict__ out)
{
    __shared__ float red[32];
    int row = blockIdx.x;
    const float* xr = x + (size_t)row * DMODEL;
    float s = 0.f, s2 = 0.f;
    for (int i = threadIdx.x; i < DMODEL; i += blockDim.x) {
        float v = xr[i];
        s += v; s2 += v * v;
    }
    #pragma unroll
    for (int o = 16; o > 0; o >>= 1) {
        s  += __shfl_down_sync(0xffffffff, s,  o);
        s2 += __shfl_down_sync(0xffffffff, s2, o);
    }
    int lane = threadIdx.x & 31, wid = threadIdx.x >> 5;
    if (lane == 0) { red[wid] = s; red[wid + 16] = s2; }
    __syncthreads();
    if (wid == 0) {
        int nw = blockDim.x >> 5;
        s  = (lane < nw) ? red[lane]      : 0.f;
        s2 = (lane < nw) ? red[lane + 16] : 0.f;
        #pragma unroll
        for (int o = 16; o > 0; o >>= 1) {
            s  += __shfl_down_sync(0xffffffff, s,  o);
            s2 += __shfl_down_sync(0xffffffff, s2, o);
        }
        if (lane == 0) { red[0] = s; red[1] = s2; }
    }
    __syncthreads();
    float mu  = red[0] / DMODEL;
    float var = red[1] / DMODEL - mu * mu;
    float rstd = rsqrtf(var + 1e-5f);
    for (int i = threadIdx.x; i < DMODEL; i += blockDim.x) {
        float v = (xr[i] - mu) * rstd * w[i] + b[i];
        out[(size_t)row * DMODEL + i] = __float2half_rn(v);
    }
}

// ---------------- host launcher ----------------
extern "C" void kernel_launch(void* const* d_in, const int* in_sizes, int n_in,
                              void* d_out, int out_size)
{
    const int*   x      = (const int*)  d_in[0];
    const float* emb    = (const float*)d_in[1];
    const float* in_w   = (const float*)d_in[2];
    const float* conv_w = (const float*)d_in[3];
    const float* conv_b = (const float*)d_in[4];
    const float* xp_w   = (const float*)d_in[5];
    const float* dt_w   = (const float*)d_in[6];
    const float* dt_b   = (const float*)d_in[7];
    const float* A_log  = (const float*)d_in[8];
    const float* Dp     = (const float*)d_in[9];
    const float* out_w  = (const float*)d_in[10];
    const float* ln_w   = (const float*)d_in[11];
    const float* ln_b   = (const float*)d_in[12];
    float* out = (float*)d_out;

    float *h, *xz, *xc, *xdbl, *dtb;
    __half *xdblh, *yh, *lnh, *hh, *xch, *embh, *inwh, *outwh, *xpwh, *dtwh;
    cudaGetSymbolAddress((void**)&h,     g_h);
    cudaGetSymbolAddress((void**)&xz,    g_xz);
    cudaGetSymbolAddress((void**)&xc,    g_xc);
    cudaGetSymbolAddress((void**)&xdbl,  g_xdbl);
    cudaGetSymbolAddress((void**)&xdblh, g_xdblh);
    cudaGetSymbolAddress((void**)&dtb,   g_dt);
    cudaGetSymbolAddress((void**)&yh,    g_yh);
    cudaGetSymbolAddress((void**)&lnh,   g_lnh);
    cudaGetSymbolAddress((void**)&hh,    g_hh);
    cudaGetSymbolAddress((void**)&xch,   g_xch);
    cudaGetSymbolAddress((void**)&embh,  g_embh);
    cudaGetSymbolAddress((void**)&inwh,  g_inwh);
    cudaGetSymbolAddress((void**)&outwh, g_outwh);
    cudaGetSymbolAddress((void**)&xpwh,  g_xpwh);
    cudaGetSymbolAddress((void**)&dtwh,  g_dtwh);

    cudaFuncSetAttribute(gemm_f16, cudaFuncAttributeMaxDynamicSharedMemorySize,
                         GEMM_SMEM);

    // launches 1-4, then #5 = in_proj gemm_f16 (ncu -s 5 captures the 5th launch)
    embed_kernel<<<(BL * DMODEL + 255) / 256, 256>>>(x, emb, h, hh);             // 1
    cvt_f16_kernel<<<(VOCAB * DMODEL / 4 + 255) / 256, 256>>>(
        (const float4*)emb, (uint2*)embh, VOCAB * DMODEL / 4);                   // 2
    cvt_f16_kernel<<<(NLAYERS * 2 * DINNER * DMODEL / 4 + 255) / 256, 256>>>(
        (const float4*)in_w, (uint2*)inwh, NLAYERS * 2 * DINNER * DMODEL / 4);   // 3
    cvt_f16_kernel<<<(NLAYERS * DMODEL * DINNER / 4 + 255) / 256, 256>>>(
        (const float4*)out_w, (uint2*)outwh, NLAYERS * DMODEL * DINNER / 4);     // 4

    for (int i = 0; i < NLAYERS; i++) {
        // in_proj: xz(2048,3072) = h_f16 @ in_w_f16^T                           // 5 (i=0)
        gemm_f16<<<dim3(BL / FTM, 2 * DINNER / FTN), 256, GEMM_SMEM>>>(
            hh, inwh + (size_t)i * 2 * DINNER * DMODEL, xz, nullptr, nullptr,
            BL, 2 * DINNER, DMODEL, DMODEL, DMODEL, 0);

        if (i == 0) {
            xpw_pad_kernel<<<(NLAYERS * 128 * DINNER + 255) / 256, 256>>>(xp_w, xpwh);
            dtw_pad_kernel<<<(NLAYERS * DINNER * 64 + 255) / 256, 256>>>(dt_w, dtwh);
        }

        conv_silu_kernel<<<(BL * DINNER + 255) / 256, 256>>>(
            xz, conv_w + (size_t)i * DINNER * DCONV, conv_b + (size_t)i * DINNER,
            xc, xch);

        // x_proj: xdbl(2048,128) fp32+fp16 = xc_f16 @ xp_w_pad^T
        gemm_f16<<<dim3(BL / FTM, 1), 256, GEMM_SMEM>>>(
            xch, xpwh + (size_t)i * 128 * DINNER, xdbl, xdblh, nullptr,
            BL, 128, DINNER, DINNER, DINNER, 4);

        // dt: softplus(xdblh[:, :64] @ dtwh^T + dt_b), K=64
        gemm_f16<<<dim3(BL / FTM, DINNER / FTN), 256, GEMM_SMEM>>>(
            xdblh, dtwh + (size_t)i * DINNER * 64, dtb, nullptr,
            dt_b + (size_t)i * DINNER,
            BL, DINNER, 64, XDLD, 64, 1);

        scan_kernel<<<(BB * DINNER * 16 + 255) / 256, 256>>>(
            xc, dtb, xdbl, xz, A_log + (size_t)i * DINNER * DSTATE,
            Dp + (size_t)i * DINNER, yh);

        // out_proj + residual + fp16 mirror: h += y @ out_w^T; hh = f16(h)
        gemm_f16<<<dim3(BL / FTM, DMODEL / FTN), 256, GEMM_SMEM>>>(
            yh, outwh + (size_t)i * DMODEL * DINNER, h, hh, nullptr,
            BL, DMODEL, DINNER, DINNER, DINNER, 6);
    }

    layernorm_kernel<<<BL, 256>>>(h, ln_w, ln_b, lnh);

    // lm_head: out(2048,32000) = ln_f16 @ emb_f16^T
    gemm_f16<<<dim3(BL / FTM, VOCAB / FTN), 256, GEMM_SMEM>>>(
        lnh, embh, out, nullptr, nullptr, BL, VOCAB, DMODEL, DMODEL, DMODEL, 0);
}